// round 7
// baseline (speedup 1.0000x reference)
#include <cuda_runtime.h>
#include <math.h>

// ----------------------------------------------------------------------------
// PHomogeneousAutoencoder: fully fused per-point pipeline.
// Round-6 change: TILE=64 + in-place layer2 (no separate B buffer) shrinks
// SMEM to ~106KB -> 2 CTAs/SM (16 warps/SM) for latency hiding, while the
// 8x32 layer2 tile keeps 8pts x 4cols per thread (LDS ~16% of issue slots).
// Weight staging of one CTA overlaps compute of the co-resident CTA.
// ----------------------------------------------------------------------------

#define TILE 64
#define HDIM 128
#define AST  132   // padded row stride (floats); 132 % 32 == 4 -> bank skew
#define NTHREADS 256

// shared memory layout (in floats)
#define OFF_A   0                // 64*132 = 8448
#define OFF_W2  8448             // 128*128 = 16384
#define OFF_W1  24832            // 3*128 max
#define OFF_B1  25216
#define OFF_B2  25344
#define OFF_W3  25472            // 128*4 (stride 4, dout<=3)
#define OFF_B3  25984
#define OFF_U   25988            // 64*4
#define OFF_T   26244            // 64*4
#define SMEM_FLOATS 26500
#define SMEM_BYTES  (SMEM_FLOATS * 4)   // 106000 B -> 2 CTAs/SM

struct Params {
    const float* x;
    const float* center;
    const float* W1[5];
    const float* b1[5];
    const float* W2[5];
    const float* b2[5];
    const float* W3[5];
    const float* b3[5];
    float* out;
    int n;
};

__device__ __forceinline__ float2 ffma2(float2 a, float2 b, float2 c) {
    float2 d;
    asm("{\n\t"
        ".reg .b64 ra, rb, rc;\n\t"
        "mov.b64 ra, {%2, %3};\n\t"
        "mov.b64 rb, {%4, %5};\n\t"
        "mov.b64 rc, {%6, %7};\n\t"
        "fma.rn.f32x2 rc, ra, rb, rc;\n\t"
        "mov.b64 {%0, %1}, rc;\n\t"
        "}"
        : "=f"(d.x), "=f"(d.y)
        : "f"(a.x), "f"(a.y), "f"(b.x), "f"(b.y), "f"(c.x), "f"(c.y));
    return d;
}

__device__ __forceinline__ float softplus_f(float x) {
    // matches jax.nn.softplus = max(x,0) + log1p(exp(-|x|))
    return fmaxf(x, 0.0f) + log1pf(expf(-fabsf(x)));
}

// Stage one MLP's weights into shared memory. All 256 threads.
__device__ void load_weights(float* sm,
                             const float* __restrict__ W1, const float* __restrict__ b1,
                             const float* __restrict__ W2, const float* __restrict__ b2,
                             const float* __restrict__ W3, const float* __restrict__ b3,
                             int din, int dout) {
    __syncthreads();   // protect previous stage's readers of A/W buffers
    int t = threadIdx.x;
    const float4* g = (const float4*)W2;
    float4* s4 = (float4*)(sm + OFF_W2);
#pragma unroll
    for (int i = 0; i < 16; i++) s4[t + NTHREADS * i] = g[t + NTHREADS * i];
    for (int i = t; i < din * HDIM; i += NTHREADS) sm[OFF_W1 + i] = W1[i];
    if (t < HDIM) {
        sm[OFF_B1 + t] = b1[t];
        sm[OFF_B2 + t] = b2[t];
#pragma unroll 3
        for (int j = 0; j < dout; j++) sm[OFF_W3 + t * 4 + j] = W3[t * dout + j];
    }
    if (t < dout) sm[OFF_B3 + t] = b3[t];
    __syncthreads();
}

// layer1: A[p][j] = relu(b1[j] + sum_i in[p][i] * W1[i][j]); in stride 4.
// 256 threads: p = t>>2 (0..63), 32 output cols per thread.
template <int DIN>
__device__ void layer1(const float* __restrict__ sm_in, const float* __restrict__ sm) {
    int t = threadIdx.x;
    int p = t >> 2;
    int j0 = (t & 3) * 32;
    float* A = (float*)(sm + OFF_A);
    const float* W1s = sm + OFF_W1;
    const float* B1s = sm + OFF_B1;
    float in[DIN];
#pragma unroll
    for (int i = 0; i < DIN; i++) in[i] = sm_in[p * 4 + i];
#pragma unroll 8
    for (int j = 0; j < 32; j += 4) {
        float4 s = *(const float4*)&B1s[j0 + j];
#pragma unroll
        for (int i = 0; i < DIN; i++) {
            float4 w = *(const float4*)&W1s[i * HDIM + j0 + j];
            s.x = fmaf(in[i], w.x, s.x);
            s.y = fmaf(in[i], w.y, s.y);
            s.z = fmaf(in[i], w.z, s.z);
            s.w = fmaf(in[i], w.w, s.w);
        }
        s.x = fmaxf(s.x, 0.f); s.y = fmaxf(s.y, 0.f);
        s.z = fmaxf(s.z, 0.f); s.w = fmaxf(s.w, 0.f);
        *(float4*)&A[p * AST + j0 + j] = s;
    }
}

// layer2 (IN PLACE): A[p][j] <- relu(b2[j] + sum_k A[p][k] * W2[k][j]).
// 256 threads as 8(tx)x32(ty): tx -> 8 points strided by 8, ty -> 4 cols.
// A loads conflict-free (banks 4*tx+k0, ty broadcast); W2 loads broadcast.
// __syncthreads() between the read loop and the in-place stores.
__device__ void layer2(float* sm) {
    float* __restrict__ A = sm + OFF_A;
    const float* __restrict__ W2s = sm + OFF_W2;
    const float* __restrict__ B2s = sm + OFF_B2;
    int t = threadIdx.x;
    int tx = t & 7, ty = t >> 3;       // ty in 0..31
    int j0 = ty * 4;                    // 4 output columns
    // points handled by this thread: p = tx + 8*i, i = 0..7

    float2 acc[8][2];
    {
        float4 b4 = *(const float4*)&B2s[j0];
#pragma unroll
        for (int i = 0; i < 8; i++) {
            acc[i][0] = make_float2(b4.x, b4.y);
            acc[i][1] = make_float2(b4.z, b4.w);
        }
    }

#pragma unroll 4
    for (int k0 = 0; k0 < HDIM; k0 += 4) {
        float4 a4[8];
#pragma unroll
        for (int i = 0; i < 8; i++) a4[i] = *(const float4*)&A[(tx + 8 * i) * AST + k0];
#pragma unroll
        for (int kk = 0; kk < 4; kk++) {
            float4 w = *(const float4*)&W2s[(k0 + kk) * HDIM + j0];  // broadcast
            float2 wv0 = make_float2(w.x, w.y);
            float2 wv1 = make_float2(w.z, w.w);
#pragma unroll
            for (int i = 0; i < 8; i++) {
                float av = (kk == 0) ? a4[i].x : (kk == 1) ? a4[i].y : (kk == 2) ? a4[i].z : a4[i].w;
                float2 a2 = make_float2(av, av);
                acc[i][0] = ffma2(a2, wv0, acc[i][0]);
                acc[i][1] = ffma2(a2, wv1, acc[i][1]);
            }
        }
    }

    __syncthreads();   // all reads of A complete before in-place overwrite

#pragma unroll
    for (int i = 0; i < 8; i++) {
        float4 v = make_float4(fmaxf(acc[i][0].x, 0.f), fmaxf(acc[i][0].y, 0.f),
                               fmaxf(acc[i][1].x, 0.f), fmaxf(acc[i][1].y, 0.f));
        *(float4*)&A[(tx + 8 * i) * AST + j0] = v;
    }
}

// layer3: s[j] = b3[j] + sum_k A[p][k] * W3[k][j].  Called by threads t<64 only.
template <int DOUT>
__device__ void layer3(const float* __restrict__ sm, float* s) {
    int p = threadIdx.x;
    const float* Abuf = sm + OFF_A;
    const float* W3s = sm + OFF_W3;
    const float* B3s = sm + OFF_B3;
#pragma unroll
    for (int j = 0; j < DOUT; j++) s[j] = B3s[j];
#pragma unroll 4
    for (int k0 = 0; k0 < HDIM; k0 += 4) {
        float4 v = *(const float4*)&Abuf[p * AST + k0];
        float vv[4] = {v.x, v.y, v.z, v.w};
#pragma unroll
        for (int kk = 0; kk < 4; kk++)
#pragma unroll
            for (int j = 0; j < DOUT; j++)
                s[j] = fmaf(vv[kk], W3s[(k0 + kk) * 4 + j], s[j]);
    }
}

__global__ __launch_bounds__(NTHREADS, 2)
void pha_kernel(Params P) {
    extern __shared__ float sm[];
    int t = threadIdx.x;
    int pg = blockIdx.x * TILE;

    float c0 = P.center[0], c1 = P.center[1], c2 = P.center[2];

    // per-point registers (threads 0..63)
    float rp = 0.f, e0 = 0.f, e1 = 0.f, rrec = 0.f;
    float cb0 = 0.f, cb1 = 0.f, cb2 = 0.f, cc0 = 0.f, cc1 = 0.f, cc2 = 0.f;
    bool live = false;

    // ---- stage 0: u = unit(x - center), rp = r^2 ----
    if (t < TILE) {
        int gp = pg + t;
        live = (gp < P.n);
        float x0 = 0.f, x1 = 0.f, x2 = 0.f;
        if (live) {
            x0 = P.x[gp * 3 + 0] - c0;
            x1 = P.x[gp * 3 + 1] - c1;
            x2 = P.x[gp * 3 + 2] - c2;
        }
        float r = sqrtf(x0 * x0 + x1 * x1 + x2 * x2);
        float inv = 1.0f / (r + 1e-8f);
        sm[OFF_U + t * 4 + 0] = x0 * inv;
        sm[OFF_U + t * 4 + 1] = x1 * inv;
        sm[OFF_U + t * 4 + 2] = x2 * inv;
        sm[OFF_U + t * 4 + 3] = 0.f;
        sm[OFF_T + t * 4 + 0] = 0.f;
        sm[OFF_T + t * 4 + 1] = 0.f;
        sm[OFF_T + t * 4 + 2] = 0.f;
        sm[OFF_T + t * 4 + 3] = 0.f;
        rp = r * r;
    }

    // ---- MLP ea: u -> e (dout=2), then unit ----
    load_weights(sm, P.W1[0], P.b1[0], P.W2[0], P.b2[0], P.W3[0], P.b3[0], 3, 2);
    layer1<3>(sm + OFF_U, sm);
    __syncthreads();
    layer2(sm);
    __syncthreads();
    if (t < TILE) {
        float s[2];
        layer3<2>(sm, s);
        float n = sqrtf(s[0] * s[0] + s[1] * s[1]);
        float inv = 1.0f / (n + 1e-8f);
        e0 = s[0] * inv;
        e1 = s[1] * inv;
    }

    // ---- MLP em: u -> a = softplus(.[0]) ; then w, theta, log r_w ----
    load_weights(sm, P.W1[1], P.b1[1], P.W2[1], P.b2[1], P.W3[1], P.b3[1], 3, 1);
    layer1<3>(sm + OFF_U, sm);
    __syncthreads();
    layer2(sm);
    __syncthreads();
    if (t < TILE) {
        float s[1];
        layer3<1>(sm, s);
        float a = softplus_f(s[0]);
        float w0 = rp * a * e0;
        float w1 = rp * a * e1;
        float rw = sqrtf(w0 * w0 + w1 * w1);
        rrec = sqrtf(rw);                      // rw^(1/P), P=2
        float it = 1.0f / (rw + 1e-8f);
        sm[OFF_T + t * 4 + 0] = w0 * it;       // theta0
        sm[OFF_T + t * 4 + 1] = w1 * it;       // theta1
        sm[OFF_T + t * 4 + 2] = logf(rw + 1e-8f);
    }

    // ---- MLP db: theta -> c_base (dout=3), unit ----
    load_weights(sm, P.W1[2], P.b1[2], P.W2[2], P.b2[2], P.W3[2], P.b3[2], 2, 3);
    layer1<2>(sm + OFF_T, sm);
    __syncthreads();
    layer2(sm);
    __syncthreads();
    if (t < TILE) {
        float s[3];
        layer3<3>(sm, s);
        float n = sqrtf(s[0] * s[0] + s[1] * s[1] + s[2] * s[2]);
        float inv = 1.0f / (n + 1e-8f);
        cb0 = s[0] * inv; cb1 = s[1] * inv; cb2 = s[2] * inv;
    }

    // ---- MLP dc: ci = [theta, log r_w] -> c_corr (dout=3) ----
    load_weights(sm, P.W1[3], P.b1[3], P.W2[3], P.b2[3], P.W3[3], P.b3[3], 3, 3);
    layer1<3>(sm + OFF_T, sm);
    __syncthreads();
    layer2(sm);
    __syncthreads();
    if (t < TILE) {
        float s[3];
        layer3<3>(sm, s);
        cc0 = s[0]; cc1 = s[1]; cc2 = s[2];
    }

    // ---- MLP dm: theta -> b = softplus(.[0]); final output ----
    load_weights(sm, P.W1[4], P.b1[4], P.W2[4], P.b2[4], P.W3[4], P.b3[4], 2, 1);
    layer1<2>(sm + OFF_T, sm);
    __syncthreads();
    layer2(sm);
    __syncthreads();
    if (t < TILE && live) {
        float s[1];
        layer3<1>(sm, s);
        float b = softplus_f(s[0]);
        float v0 = cb0 + cc0, v1 = cb1 + cc1, v2 = cb2 + cc2;
        float n = sqrtf(v0 * v0 + v1 * v1 + v2 * v2);
        float inv = 1.0f / (n + 1e-8f);
        float scale = rrec * b * inv;
        int gp = pg + t;
        P.out[gp * 3 + 0] = c0 + scale * v0;
        P.out[gp * 3 + 1] = c1 + scale * v1;
        P.out[gp * 3 + 2] = c2 + scale * v2;
    }
}

extern "C" void kernel_launch(void* const* d_in, const int* in_sizes, int n_in,
                              void* d_out, int out_size) {
    Params P;
    P.x = (const float*)d_in[0];
    P.center = (const float*)d_in[1];
    for (int m = 0; m < 5; m++) {
        int b = 2 + m * 6;
        P.W1[m] = (const float*)d_in[b + 0];
        P.b1[m] = (const float*)d_in[b + 1];
        P.W2[m] = (const float*)d_in[b + 2];
        P.b2[m] = (const float*)d_in[b + 3];
        P.W3[m] = (const float*)d_in[b + 4];
        P.b3[m] = (const float*)d_in[b + 5];
    }
    P.out = (float*)d_out;
    P.n = in_sizes[0] / 3;

    (void)cudaFuncSetAttribute(pha_kernel, cudaFuncAttributeMaxDynamicSharedMemorySize, SMEM_BYTES);
    int grid = (P.n + TILE - 1) / TILE;
    pha_kernel<<<grid, NTHREADS, SMEM_BYTES>>>(P);
}

// round 9
// speedup vs baseline: 1.4139x; 1.4139x over previous
#include <cuda_runtime.h>
#include <math.h>

// ----------------------------------------------------------------------------
// PHomogeneousAutoencoder: fully fused per-point pipeline.
// Round-7 design (resubmitted; prior round was an infra failure):
// TILE=256 points, 512 threads, ONE CTA/SM (~213KB smem).
// Doubles warps/SM (16 vs 8) at the R3-best LDS:FMA ratio (8pts x 8cols per
// thread). layer2 is in-place over A (no B buffer). W2 loads full-warp
// broadcast; A loads conflict-free via AST=132 phase skew.
// ----------------------------------------------------------------------------

#define TILE 256
#define HDIM 128
#define AST  132   // padded row stride (floats); 132 % 32 == 4 -> bank skew
#define NTHREADS 512

// shared memory layout (in floats)
#define OFF_A   0                // 256*132 = 33792
#define OFF_W2  33792            // 128*128 = 16384
#define OFF_W1  50176            // 3*128 max
#define OFF_B1  50560
#define OFF_B2  50688
#define OFF_W3  50816            // 128*4 (stride 4, dout<=3)
#define OFF_B3  51328
#define OFF_U   51332            // 256*4
#define OFF_T   52356            // 256*4
#define SMEM_FLOATS 53380
#define SMEM_BYTES  (SMEM_FLOATS * 4)   // 213520 B -> 1 CTA/SM, 16 warps

struct Params {
    const float* x;
    const float* center;
    const float* W1[5];
    const float* b1[5];
    const float* W2[5];
    const float* b2[5];
    const float* W3[5];
    const float* b3[5];
    float* out;
    int n;
};

__device__ __forceinline__ float2 ffma2(float2 a, float2 b, float2 c) {
    float2 d;
    asm("{\n\t"
        ".reg .b64 ra, rb, rc;\n\t"
        "mov.b64 ra, {%2, %3};\n\t"
        "mov.b64 rb, {%4, %5};\n\t"
        "mov.b64 rc, {%6, %7};\n\t"
        "fma.rn.f32x2 rc, ra, rb, rc;\n\t"
        "mov.b64 {%0, %1}, rc;\n\t"
        "}"
        : "=f"(d.x), "=f"(d.y)
        : "f"(a.x), "f"(a.y), "f"(b.x), "f"(b.y), "f"(c.x), "f"(c.y));
    return d;
}

__device__ __forceinline__ float softplus_f(float x) {
    // matches jax.nn.softplus = max(x,0) + log1p(exp(-|x|))
    return fmaxf(x, 0.0f) + log1pf(expf(-fabsf(x)));
}

// Stage one MLP's weights into shared memory. All 512 threads.
__device__ void load_weights(float* sm,
                             const float* __restrict__ W1, const float* __restrict__ b1,
                             const float* __restrict__ W2, const float* __restrict__ b2,
                             const float* __restrict__ W3, const float* __restrict__ b3,
                             int din, int dout) {
    __syncthreads();   // protect previous stage's readers of A/W buffers
    int t = threadIdx.x;
    const float4* g = (const float4*)W2;
    float4* s4 = (float4*)(sm + OFF_W2);
#pragma unroll
    for (int i = 0; i < 8; i++) s4[t + NTHREADS * i] = g[t + NTHREADS * i];
    for (int i = t; i < din * HDIM; i += NTHREADS) sm[OFF_W1 + i] = W1[i];
    if (t < HDIM) {
        sm[OFF_B1 + t] = b1[t];
        sm[OFF_B2 + t] = b2[t];
#pragma unroll 3
        for (int j = 0; j < dout; j++) sm[OFF_W3 + t * 4 + j] = W3[t * dout + j];
    }
    if (t < dout) sm[OFF_B3 + t] = b3[t];
    __syncthreads();
}

// layer1: A[p][j] = relu(b1[j] + sum_i in[p][i] * W1[i][j]); in stride 4.
// 512 threads: p = t>>1 (0..255), 64 output cols per thread.
template <int DIN>
__device__ void layer1(const float* __restrict__ sm_in, const float* __restrict__ sm) {
    int t = threadIdx.x;
    int p = t >> 1;
    int j0 = (t & 1) * 64;
    float* A = (float*)(sm + OFF_A);
    const float* W1s = sm + OFF_W1;
    const float* B1s = sm + OFF_B1;
    float in[DIN];
#pragma unroll
    for (int i = 0; i < DIN; i++) in[i] = sm_in[p * 4 + i];
#pragma unroll 4
    for (int j = 0; j < 64; j += 4) {
        float4 s = *(const float4*)&B1s[j0 + j];
#pragma unroll
        for (int i = 0; i < DIN; i++) {
            float4 w = *(const float4*)&W1s[i * HDIM + j0 + j];
            s.x = fmaf(in[i], w.x, s.x);
            s.y = fmaf(in[i], w.y, s.y);
            s.z = fmaf(in[i], w.z, s.z);
            s.w = fmaf(in[i], w.w, s.w);
        }
        s.x = fmaxf(s.x, 0.f); s.y = fmaxf(s.y, 0.f);
        s.z = fmaxf(s.z, 0.f); s.w = fmaxf(s.w, 0.f);
        *(float4*)&A[p * AST + j0 + j] = s;
    }
}

// layer2 (IN PLACE): A[p][j] <- relu(b2[j] + sum_k A[p][k] * W2[k][j]).
// 512 threads as 32(tx)x16(ty): tx -> 8 points strided by 32, ty -> 8 cols.
// W2 loads are full-warp broadcast (single ty per warp); A loads/stores are
// conflict-free per 8-lane phase (AST=132 -> start banks 4*tx mod 32 distinct).
__device__ void layer2(float* sm) {
    float* __restrict__ A = sm + OFF_A;
    const float* __restrict__ W2s = sm + OFF_W2;
    const float* __restrict__ B2s = sm + OFF_B2;
    int t = threadIdx.x;
    int tx = t & 31, ty = t >> 5;      // ty in 0..15
    int j0 = ty * 8;                    // 8 output columns
    // points handled by this thread: p = tx + 32*i, i = 0..7

    float2 acc[8][4];
    {
        float4 bA = *(const float4*)&B2s[j0];
        float4 bB = *(const float4*)&B2s[j0 + 4];
#pragma unroll
        for (int i = 0; i < 8; i++) {
            acc[i][0] = make_float2(bA.x, bA.y);
            acc[i][1] = make_float2(bA.z, bA.w);
            acc[i][2] = make_float2(bB.x, bB.y);
            acc[i][3] = make_float2(bB.z, bB.w);
        }
    }

#pragma unroll 2
    for (int k0 = 0; k0 < HDIM; k0 += 4) {
        float4 a4[8];
#pragma unroll
        for (int i = 0; i < 8; i++) a4[i] = *(const float4*)&A[(tx + 32 * i) * AST + k0];
#pragma unroll
        for (int kk = 0; kk < 4; kk++) {
            const float* wr = &W2s[(k0 + kk) * HDIM + j0];
            float4 w0 = *(const float4*)wr;        // full-warp broadcast
            float4 w1 = *(const float4*)(wr + 4);
            float2 wv[4];
            wv[0] = make_float2(w0.x, w0.y);
            wv[1] = make_float2(w0.z, w0.w);
            wv[2] = make_float2(w1.x, w1.y);
            wv[3] = make_float2(w1.z, w1.w);
#pragma unroll
            for (int i = 0; i < 8; i++) {
                float av = (kk == 0) ? a4[i].x : (kk == 1) ? a4[i].y : (kk == 2) ? a4[i].z : a4[i].w;
                float2 a2 = make_float2(av, av);
#pragma unroll
                for (int jj = 0; jj < 4; jj++) acc[i][jj] = ffma2(a2, wv[jj], acc[i][jj]);
            }
        }
    }

    __syncthreads();   // all reads of A complete before in-place overwrite

#pragma unroll
    for (int i = 0; i < 8; i++) {
        float* crow = &A[(tx + 32 * i) * AST + j0];
        float4 v0 = make_float4(fmaxf(acc[i][0].x, 0.f), fmaxf(acc[i][0].y, 0.f),
                                fmaxf(acc[i][1].x, 0.f), fmaxf(acc[i][1].y, 0.f));
        float4 v1 = make_float4(fmaxf(acc[i][2].x, 0.f), fmaxf(acc[i][2].y, 0.f),
                                fmaxf(acc[i][3].x, 0.f), fmaxf(acc[i][3].y, 0.f));
        *(float4*)crow = v0;
        *(float4*)(crow + 4) = v1;
    }
}

// layer3: s[j] = b3[j] + sum_k A[p][k] * W3[k][j].  Called by threads t<256 only.
template <int DOUT>
__device__ void layer3(const float* __restrict__ sm, float* s) {
    int p = threadIdx.x;
    const float* Abuf = sm + OFF_A;
    const float* W3s = sm + OFF_W3;
    const float* B3s = sm + OFF_B3;
#pragma unroll
    for (int j = 0; j < DOUT; j++) s[j] = B3s[j];
#pragma unroll 4
    for (int k0 = 0; k0 < HDIM; k0 += 4) {
        float4 v = *(const float4*)&Abuf[p * AST + k0];
        float vv[4] = {v.x, v.y, v.z, v.w};
#pragma unroll
        for (int kk = 0; kk < 4; kk++)
#pragma unroll
            for (int j = 0; j < DOUT; j++)
                s[j] = fmaf(vv[kk], W3s[(k0 + kk) * 4 + j], s[j]);
    }
}

__global__ __launch_bounds__(NTHREADS, 1)
void pha_kernel(Params P) {
    extern __shared__ float sm[];
    int t = threadIdx.x;
    int pg = blockIdx.x * TILE;

    float c0 = P.center[0], c1 = P.center[1], c2 = P.center[2];

    // per-point registers (threads 0..255)
    float rp = 0.f, e0 = 0.f, e1 = 0.f, rrec = 0.f;
    float cb0 = 0.f, cb1 = 0.f, cb2 = 0.f, cc0 = 0.f, cc1 = 0.f, cc2 = 0.f;
    bool live = false;

    // ---- stage 0: u = unit(x - center), rp = r^2 ----
    if (t < TILE) {
        int gp = pg + t;
        live = (gp < P.n);
        float x0 = 0.f, x1 = 0.f, x2 = 0.f;
        if (live) {
            x0 = P.x[gp * 3 + 0] - c0;
            x1 = P.x[gp * 3 + 1] - c1;
            x2 = P.x[gp * 3 + 2] - c2;
        }
        float r = sqrtf(x0 * x0 + x1 * x1 + x2 * x2);
        float inv = 1.0f / (r + 1e-8f);
        sm[OFF_U + t * 4 + 0] = x0 * inv;
        sm[OFF_U + t * 4 + 1] = x1 * inv;
        sm[OFF_U + t * 4 + 2] = x2 * inv;
        sm[OFF_U + t * 4 + 3] = 0.f;
        sm[OFF_T + t * 4 + 0] = 0.f;
        sm[OFF_T + t * 4 + 1] = 0.f;
        sm[OFF_T + t * 4 + 2] = 0.f;
        sm[OFF_T + t * 4 + 3] = 0.f;
        rp = r * r;
    }

    // ---- MLP ea: u -> e (dout=2), then unit ----
    load_weights(sm, P.W1[0], P.b1[0], P.W2[0], P.b2[0], P.W3[0], P.b3[0], 3, 2);
    layer1<3>(sm + OFF_U, sm);
    __syncthreads();
    layer2(sm);
    __syncthreads();
    if (t < TILE) {
        float s[2];
        layer3<2>(sm, s);
        float n = sqrtf(s[0] * s[0] + s[1] * s[1]);
        float inv = 1.0f / (n + 1e-8f);
        e0 = s[0] * inv;
        e1 = s[1] * inv;
    }

    // ---- MLP em: u -> a = softplus(.[0]) ; then w, theta, log r_w ----
    load_weights(sm, P.W1[1], P.b1[1], P.W2[1], P.b2[1], P.W3[1], P.b3[1], 3, 1);
    layer1<3>(sm + OFF_U, sm);
    __syncthreads();
    layer2(sm);
    __syncthreads();
    if (t < TILE) {
        float s[1];
        layer3<1>(sm, s);
        float a = softplus_f(s[0]);
        float w0 = rp * a * e0;
        float w1 = rp * a * e1;
        float rw = sqrtf(w0 * w0 + w1 * w1);
        rrec = sqrtf(rw);                      // rw^(1/P), P=2
        float it = 1.0f / (rw + 1e-8f);
        sm[OFF_T + t * 4 + 0] = w0 * it;       // theta0
        sm[OFF_T + t * 4 + 1] = w1 * it;       // theta1
        sm[OFF_T + t * 4 + 2] = logf(rw + 1e-8f);
    }

    // ---- MLP db: theta -> c_base (dout=3), unit ----
    load_weights(sm, P.W1[2], P.b1[2], P.W2[2], P.b2[2], P.W3[2], P.b3[2], 2, 3);
    layer1<2>(sm + OFF_T, sm);
    __syncthreads();
    layer2(sm);
    __syncthreads();
    if (t < TILE) {
        float s[3];
        layer3<3>(sm, s);
        float n = sqrtf(s[0] * s[0] + s[1] * s[1] + s[2] * s[2]);
        float inv = 1.0f / (n + 1e-8f);
        cb0 = s[0] * inv; cb1 = s[1] * inv; cb2 = s[2] * inv;
    }

    // ---- MLP dc: ci = [theta, log r_w] -> c_corr (dout=3) ----
    load_weights(sm, P.W1[3], P.b1[3], P.W2[3], P.b2[3], P.W3[3], P.b3[3], 3, 3);
    layer1<3>(sm + OFF_T, sm);
    __syncthreads();
    layer2(sm);
    __syncthreads();
    if (t < TILE) {
        float s[3];
        layer3<3>(sm, s);
        cc0 = s[0]; cc1 = s[1]; cc2 = s[2];
    }

    // ---- MLP dm: theta -> b = softplus(.[0]); final output ----
    load_weights(sm, P.W1[4], P.b1[4], P.W2[4], P.b2[4], P.W3[4], P.b3[4], 2, 1);
    layer1<2>(sm + OFF_T, sm);
    __syncthreads();
    layer2(sm);
    __syncthreads();
    if (t < TILE && live) {
        float s[1];
        layer3<1>(sm, s);
        float b = softplus_f(s[0]);
        float v0 = cb0 + cc0, v1 = cb1 + cc1, v2 = cb2 + cc2;
        float n = sqrtf(v0 * v0 + v1 * v1 + v2 * v2);
        float inv = 1.0f / (n + 1e-8f);
        float scale = rrec * b * inv;
        int gp = pg + t;
        P.out[gp * 3 + 0] = c0 + scale * v0;
        P.out[gp * 3 + 1] = c1 + scale * v1;
        P.out[gp * 3 + 2] = c2 + scale * v2;
    }
}

extern "C" void kernel_launch(void* const* d_in, const int* in_sizes, int n_in,
                              void* d_out, int out_size) {
    Params P;
    P.x = (const float*)d_in[0];
    P.center = (const float*)d_in[1];
    for (int m = 0; m < 5; m++) {
        int b = 2 + m * 6;
        P.W1[m] = (const float*)d_in[b + 0];
        P.b1[m] = (const float*)d_in[b + 1];
        P.W2[m] = (const float*)d_in[b + 2];
        P.b2[m] = (const float*)d_in[b + 3];
        P.W3[m] = (const float*)d_in[b + 4];
        P.b3[m] = (const float*)d_in[b + 5];
    }
    P.out = (float*)d_out;
    P.n = in_sizes[0] / 3;

    (void)cudaFuncSetAttribute(pha_kernel, cudaFuncAttributeMaxDynamicSharedMemorySize, SMEM_BYTES);
    int grid = (P.n + TILE - 1) / TILE;
    pha_kernel<<<grid, NTHREADS, SMEM_BYTES>>>(P);
}

// round 12
// speedup vs baseline: 2.6426x; 1.8690x over previous
#include <cuda_runtime.h>
#include <cuda_bf16.h>
#include <math.h>
#include <stdint.h>

// ----------------------------------------------------------------------------
// PHomogeneousAutoencoder, mma.sync edition (compute_100-safe; tcgen05 is not
// available in this toolchain's PTX target).
// layer2 = bf16x3 split GEMM (AhBh + AhBl + AlBh, fp32 accum) on HMMA
// (mma.sync.m16n8k16) with ldmatrix operands. Warp-local dataflow: warp w owns
// points [16w,16w+16) end-to-end (layer1 -> mma -> epilogue-in-registers ->
// glue); per stage only weight staging needs block barriers.
// R11 fix: W2 staged [k][j] (natural orientation) + ldmatrix.x2.trans over
// k-rows -- the R10 combination (BT[j][k] + trans) had the B fragment's k/n
// roles swapped.
// ----------------------------------------------------------------------------

#define TILE 256
#define NTHREADS 512
#define HDIM 128
#define ASTB 272    // row stride in bytes (136 bf16); 68 words -> 4-bank skew/row

// SMEM byte offsets
#define OFF_A_HI  0         // 256 x 272 = 69632
#define OFF_A_LO  69632     // 69632
#define OFF_B_HI  139264    // 128 x 272 = 34816  (W2 hi, [k][j])
#define OFF_B_LO  174080    // 34816              (W2 lo, [k][j])
#define OFF_W1    208896    // 3*128 fp32
#define OFF_B1    210432    // 128 fp32
#define OFF_B2    210944    // 128 fp32
#define OFF_W3    211456    // 128*4 fp32 (stride 4)
#define OFF_B3    213504    // 4 fp32
#define OFF_U     213520    // 256*4 fp32
#define OFF_T     217616    // 256*4 fp32
#define SMEM_BYTES 221712

struct Params {
    const float* x;
    const float* center;
    const float* W1[5];
    const float* b1[5];
    const float* W2[5];
    const float* b2[5];
    const float* W3[5];
    const float* b3[5];
    float* out;
    int n;
};

static __device__ __forceinline__ uint32_t smem_u32_of(const void* p) {
    uint32_t a;
    asm("{ .reg .u64 t; cvta.to.shared.u64 t, %1; cvt.u32.u64 %0, t; }" : "=r"(a) : "l"(p));
    return a;
}

static __device__ __forceinline__ void ldsm4(uint32_t& r0, uint32_t& r1, uint32_t& r2,
                                             uint32_t& r3, uint32_t addr) {
    asm volatile("ldmatrix.sync.aligned.m8n8.x4.shared.b16 {%0,%1,%2,%3}, [%4];"
                 : "=r"(r0), "=r"(r1), "=r"(r2), "=r"(r3) : "r"(addr));
}
static __device__ __forceinline__ void ldsm2t(uint32_t& r0, uint32_t& r1, uint32_t addr) {
    asm volatile("ldmatrix.sync.aligned.m8n8.x2.trans.shared.b16 {%0,%1}, [%2];"
                 : "=r"(r0), "=r"(r1) : "r"(addr));
}
static __device__ __forceinline__ void mma16816(float* d, uint32_t a0, uint32_t a1,
                                                uint32_t a2, uint32_t a3,
                                                uint32_t b0, uint32_t b1) {
    asm volatile(
        "mma.sync.aligned.m16n8k16.row.col.f32.bf16.bf16.f32 "
        "{%0,%1,%2,%3}, {%4,%5,%6,%7}, {%8,%9}, {%0,%1,%2,%3};"
        : "+f"(d[0]), "+f"(d[1]), "+f"(d[2]), "+f"(d[3])
        : "r"(a0), "r"(a1), "r"(a2), "r"(a3), "r"(b0), "r"(b1));
}

static __device__ __forceinline__ float softplus_f(float x) {
    return fmaxf(x, 0.0f) + log1pf(expf(-fabsf(x)));
}

static __device__ __forceinline__ uint32_t pack_bf(__nv_bfloat16 a, __nv_bfloat16 b) {
    return (uint32_t)__bfloat16_as_ushort(a) | ((uint32_t)__bfloat16_as_ushort(b) << 16);
}

static __device__ __forceinline__ void store2(char* ah, char* al, int col, float x0, float x1) {
    __nv_bfloat16 h0 = __float2bfloat16(x0), h1 = __float2bfloat16(x1);
    __nv_bfloat16 l0 = __float2bfloat16(x0 - __bfloat162float(h0));
    __nv_bfloat16 l1 = __float2bfloat16(x1 - __bfloat162float(h1));
    *(uint32_t*)(ah + col * 2) = pack_bf(h0, h1);
    *(uint32_t*)(al + col * 2) = pack_bf(l0, l1);
}

// Stage weights. Block-wide; sync before (previous readers) and after.
static __device__ void load_weights(char* smem,
                                    const float* __restrict__ W1, const float* __restrict__ b1,
                                    const float* __restrict__ W2, const float* __restrict__ b2,
                                    const float* __restrict__ W3, const float* __restrict__ b3,
                                    int din, int dout) {
    __syncthreads();
    int t = threadIdx.x;
    char* bh = smem + OFF_B_HI;
    char* bl = smem + OFF_B_LO;
#pragma unroll 4
    for (int i = 0; i < 32; i++) {
        int idx = t + NTHREADS * i;          // coalesced over W2[k][j]
        float w = W2[idx];
        int k = idx >> 7, j = idx & 127;
        __nv_bfloat16 h = __float2bfloat16(w);
        __nv_bfloat16 l = __float2bfloat16(w - __bfloat162float(h));
        uint32_t off = (uint32_t)k * ASTB + (uint32_t)j * 2;   // natural [k][j]
        *(__nv_bfloat16*)(bh + off) = h;
        *(__nv_bfloat16*)(bl + off) = l;
    }
    float* W1s = (float*)(smem + OFF_W1);
    for (int i = t; i < din * HDIM; i += NTHREADS) W1s[i] = W1[i];
    if (t < HDIM) {
        ((float*)(smem + OFF_B1))[t] = b1[t];
        ((float*)(smem + OFF_B2))[t] = b2[t];
#pragma unroll 3
        for (int j = 0; j < dout; j++) ((float*)(smem + OFF_W3))[t * 4 + j] = W3[t * dout + j];
    }
    if (t < dout) ((float*)(smem + OFF_B3))[t] = b3[t];
    __syncthreads();
}

// layer1: thread t handles point p=t>>1 (warp-local rows!), 64 cols.
template <int DIN>
static __device__ void layer1(char* smem, const float* __restrict__ in_base) {
    int t = threadIdx.x;
    int p = t >> 1;
    int j0 = (t & 1) * 64;
    const float* W1s = (const float*)(smem + OFF_W1);
    const float* B1s = (const float*)(smem + OFF_B1);
    char* ah = smem + OFF_A_HI + p * ASTB;
    char* al = smem + OFF_A_LO + p * ASTB;
    float in[DIN];
#pragma unroll
    for (int i = 0; i < DIN; i++) in[i] = in_base[p * 4 + i];
#pragma unroll 4
    for (int j = 0; j < 64; j += 4) {
        float4 s = *(const float4*)&B1s[j0 + j];
#pragma unroll
        for (int i = 0; i < DIN; i++) {
            float4 w = *(const float4*)&W1s[i * HDIM + j0 + j];
            s.x = fmaf(in[i], w.x, s.x);
            s.y = fmaf(in[i], w.y, s.y);
            s.z = fmaf(in[i], w.z, s.z);
            s.w = fmaf(in[i], w.w, s.w);
        }
        s.x = fmaxf(s.x, 0.f); s.y = fmaxf(s.y, 0.f);
        s.z = fmaxf(s.z, 0.f); s.w = fmaxf(s.w, 0.f);
        store2(ah, al, j0 + j, s.x, s.y);
        store2(ah, al, j0 + j + 2, s.z, s.w);
    }
}

// bf16x3 MMA over this warp's 16 rows, all 128 cols, K=128.
// A fragments: ldsm4 non-trans on A[row][k].  B fragments: ldsm2t (trans) on
// W2[k][j]: matrix0 = k-rows [16ks,16ks+8), matrix1 = k-rows +8; col = j tile.
static __device__ void mma_stage(char* smem, float acc[16][4]) {
    int t = threadIdx.x;
    int w = t >> 5, l = t & 31;
    uint32_t aH_base = smem_u32_of(smem + OFF_A_HI) + (uint32_t)(w * 16) * ASTB;
    uint32_t aL_base = smem_u32_of(smem + OFF_A_LO) + (uint32_t)(w * 16) * ASTB;
    uint32_t bH_base = smem_u32_of(smem + OFF_B_HI);
    uint32_t bL_base = smem_u32_of(smem + OFF_B_LO);
    int r = l & 7, sel = l >> 3;
    uint32_t a_off = (uint32_t)((r + (sel & 1) * 8) * ASTB + (sel >> 1) * 16);
    uint32_t b_row = (uint32_t)(((sel & 1) * 8 + r) * ASTB);   // lanes 0-7: k rows, 8-15: k+8

#pragma unroll 1
    for (int ks = 0; ks < 8; ks++) {
        uint32_t a_kb = (uint32_t)ks * 32;          // 16 k-cols * 2B in A rows
        uint32_t b_kb = (uint32_t)(ks * 16) * ASTB; // 16 k-rows in B
        uint32_t aH0, aH1, aH2, aH3, aL0, aL1, aL2, aL3;
        ldsm4(aH0, aH1, aH2, aH3, aH_base + a_off + a_kb);
        ldsm4(aL0, aL1, aL2, aL3, aL_base + a_off + a_kb);
#pragma unroll
        for (int n = 0; n < 16; n++) {
            uint32_t baddr = b_kb + b_row + (uint32_t)n * 16;  // j tile = 8 cols * 2B
            uint32_t bh0, bh1, bl0, bl1;
            ldsm2t(bh0, bh1, bH_base + baddr);
            ldsm2t(bl0, bl1, bL_base + baddr);
            mma16816(acc[n], aH0, aH1, aH2, aH3, bh0, bh1);
            mma16816(acc[n], aH0, aH1, aH2, aH3, bl0, bl1);
            mma16816(acc[n], aL0, aL1, aL2, aL3, bh0, bh1);
        }
    }
}

// Epilogue: bias+ReLU+layer3 straight from fragments; quad shfl reduce.
template <int DOUT>
static __device__ void epilogue(char* smem, float acc[16][4], float* sa, float* sb) {
    const float* B2s = (const float*)(smem + OFF_B2);
    const float* W3s = (const float*)(smem + OFF_W3);
    const float* B3s = (const float*)(smem + OFF_B3);
    int qi = threadIdx.x & 3;
    float sa_[DOUT], sb_[DOUT];
#pragma unroll
    for (int jo = 0; jo < DOUT; jo++) { sa_[jo] = 0.f; sb_[jo] = 0.f; }
#pragma unroll
    for (int n = 0; n < 16; n++) {
        int j = n * 8 + qi * 2;
        float2 b2 = *(const float2*)&B2s[j];
        float vA0 = fmaxf(acc[n][0] + b2.x, 0.f);
        float vA1 = fmaxf(acc[n][1] + b2.y, 0.f);
        float vB0 = fmaxf(acc[n][2] + b2.x, 0.f);
        float vB1 = fmaxf(acc[n][3] + b2.y, 0.f);
        float4 w30 = *(const float4*)&W3s[j * 4];
        float4 w31 = *(const float4*)&W3s[(j + 1) * 4];
        float w30a[4] = {w30.x, w30.y, w30.z, w30.w};
        float w31a[4] = {w31.x, w31.y, w31.z, w31.w};
#pragma unroll
        for (int jo = 0; jo < DOUT; jo++) {
            sa_[jo] = fmaf(vA0, w30a[jo], fmaf(vA1, w31a[jo], sa_[jo]));
            sb_[jo] = fmaf(vB0, w30a[jo], fmaf(vB1, w31a[jo], sb_[jo]));
        }
    }
#pragma unroll
    for (int jo = 0; jo < DOUT; jo++) {
#pragma unroll
        for (int m = 1; m < 4; m <<= 1) {
            sa_[jo] += __shfl_xor_sync(0xFFFFFFFFu, sa_[jo], m);
            sb_[jo] += __shfl_xor_sync(0xFFFFFFFFu, sb_[jo], m);
        }
        sa[jo] = sa_[jo] + B3s[jo];
        sb[jo] = sb_[jo] + B3s[jo];
    }
}

template <int DIN, int DOUT>
static __device__ void run_mlp(char* smem, const Params& P, int m, int in_off,
                               float* sa, float* sb) {
    load_weights(smem, P.W1[m], P.b1[m], P.W2[m], P.b2[m], P.W3[m], P.b3[m], DIN, DOUT);
    layer1<DIN>(smem, (const float*)(smem + in_off));
    __syncwarp();
    float acc[16][4];
#pragma unroll
    for (int n = 0; n < 16; n++)
#pragma unroll
        for (int k = 0; k < 4; k++) acc[n][k] = 0.f;
    mma_stage(smem, acc);
    epilogue<DOUT>(smem, acc, sa, sb);
}

__global__ __launch_bounds__(NTHREADS, 1)
void pha_kernel(Params P) {
    extern __shared__ char smem[];
    int t = threadIdx.x;
    int w = t >> 5, l = t & 31, g = l >> 2, qi = l & 3;
    int pg = blockIdx.x * TILE;
    int la = w * 16 + g, lb = la + 8;       // local point indices (this lane owns 2)
    int pa = pg + la, pb = pg + lb;
    bool live_a = pa < P.n, live_b = pb < P.n;

    float c0 = P.center[0], c1 = P.center[1], c2 = P.center[2];
    float* U = (float*)(smem + OFF_U);
    float* T = (float*)(smem + OFF_T);

    // ---- stage 0: u = unit(x-center), rp = r^2 (lane-owned, qi==0 writes) ----
    float rp_a, rp_b;
    {
        float x0 = 0.f, x1 = 0.f, x2 = 0.f;
        if (live_a) { x0 = P.x[pa*3+0]-c0; x1 = P.x[pa*3+1]-c1; x2 = P.x[pa*3+2]-c2; }
        float r = sqrtf(x0*x0 + x1*x1 + x2*x2);
        float inv = 1.0f / (r + 1e-8f);
        if (qi == 0) { U[la*4+0] = x0*inv; U[la*4+1] = x1*inv; U[la*4+2] = x2*inv; }
        rp_a = r * r;
        x0 = x1 = x2 = 0.f;
        if (live_b) { x0 = P.x[pb*3+0]-c0; x1 = P.x[pb*3+1]-c1; x2 = P.x[pb*3+2]-c2; }
        r = sqrtf(x0*x0 + x1*x1 + x2*x2);
        inv = 1.0f / (r + 1e-8f);
        if (qi == 0) { U[lb*4+0] = x0*inv; U[lb*4+1] = x1*inv; U[lb*4+2] = x2*inv; }
        rp_b = r * r;
    }

    // ---- MLP ea: u -> e (dout=2), unit ----
    float e0a, e1a, e0b, e1b;
    {
        float sa[2], sb[2];
        run_mlp<3, 2>(smem, P, 0, OFF_U, sa, sb);
        float n = sqrtf(sa[0]*sa[0] + sa[1]*sa[1]);
        float inv = 1.0f / (n + 1e-8f);
        e0a = sa[0]*inv; e1a = sa[1]*inv;
        n = sqrtf(sb[0]*sb[0] + sb[1]*sb[1]);
        inv = 1.0f / (n + 1e-8f);
        e0b = sb[0]*inv; e1b = sb[1]*inv;
    }

    // ---- MLP em: u -> a; w, theta, log r_w ----
    float rrec_a, rrec_b;
    {
        float sa[1], sb[1];
        run_mlp<3, 1>(smem, P, 1, OFF_U, sa, sb);
        float a = softplus_f(sa[0]);
        float w0 = rp_a * a * e0a, w1 = rp_a * a * e1a;
        float rw = sqrtf(w0*w0 + w1*w1);
        rrec_a = sqrtf(rw);
        float it = 1.0f / (rw + 1e-8f);
        if (qi == 0) { T[la*4+0] = w0*it; T[la*4+1] = w1*it; T[la*4+2] = logf(rw + 1e-8f); }
        a = softplus_f(sb[0]);
        w0 = rp_b * a * e0b; w1 = rp_b * a * e1b;
        rw = sqrtf(w0*w0 + w1*w1);
        rrec_b = sqrtf(rw);
        it = 1.0f / (rw + 1e-8f);
        if (qi == 0) { T[lb*4+0] = w0*it; T[lb*4+1] = w1*it; T[lb*4+2] = logf(rw + 1e-8f); }
    }

    // ---- MLP db: theta -> c_base (dout=3), unit ----
    float ca0, ca1, ca2, cb0, cb1, cb2;
    {
        float sa[3], sb[3];
        run_mlp<2, 3>(smem, P, 2, OFF_T, sa, sb);
        float n = sqrtf(sa[0]*sa[0] + sa[1]*sa[1] + sa[2]*sa[2]);
        float inv = 1.0f / (n + 1e-8f);
        ca0 = sa[0]*inv; ca1 = sa[1]*inv; ca2 = sa[2]*inv;
        n = sqrtf(sb[0]*sb[0] + sb[1]*sb[1] + sb[2]*sb[2]);
        inv = 1.0f / (n + 1e-8f);
        cb0 = sb[0]*inv; cb1 = sb[1]*inv; cb2 = sb[2]*inv;
    }

    // ---- MLP dc: [theta, log r_w] -> c_corr (dout=3); fold into c_base ----
    {
        float sa[3], sb[3];
        run_mlp<3, 3>(smem, P, 3, OFF_T, sa, sb);
        ca0 += sa[0]; ca1 += sa[1]; ca2 += sa[2];
        cb0 += sb[0]; cb1 += sb[1]; cb2 += sb[2];
    }

    // ---- MLP dm: theta -> b; final output ----
    {
        float sa[1], sb[1];
        run_mlp<2, 1>(smem, P, 4, OFF_T, sa, sb);
        if (qi == 0 && live_a) {
            float b = softplus_f(sa[0]);
            float n = sqrtf(ca0*ca0 + ca1*ca1 + ca2*ca2);
            float scale = rrec_a * b / (n + 1e-8f);
            P.out[pa*3+0] = c0 + scale * ca0;
            P.out[pa*3+1] = c1 + scale * ca1;
            P.out[pa*3+2] = c2 + scale * ca2;
        }
        if (qi == 0 && live_b) {
            float b = softplus_f(sb[0]);
            float n = sqrtf(cb0*cb0 + cb1*cb1 + cb2*cb2);
            float scale = rrec_b * b / (n + 1e-8f);
            P.out[pb*3+0] = c0 + scale * cb0;
            P.out[pb*3+1] = c1 + scale * cb1;
            P.out[pb*3+2] = c2 + scale * cb2;
        }
    }
}

extern "C" void kernel_launch(void* const* d_in, const int* in_sizes, int n_in,
                              void* d_out, int out_size) {
    Params P;
    P.x = (const float*)d_in[0];
    P.center = (const float*)d_in[1];
    for (int m = 0; m < 5; m++) {
        int b = 2 + m * 6;
        P.W1[m] = (const float*)d_in[b + 0];
        P.b1[m] = (const float*)d_in[b + 1];
        P.W2[m] = (const float*)d_in[b + 2];
        P.b2[m] = (const float*)d_in[b + 3];
        P.W3[m] = (const float*)d_in[b + 4];
        P.b3[m] = (const float*)d_in[b + 5];
    }
    P.out = (float*)d_out;
    P.n = in_sizes[0] / 3;

    (void)cudaFuncSetAttribute(pha_kernel, cudaFuncAttributeMaxDynamicSharedMemorySize, SMEM_BYTES);
    int grid = (P.n + TILE - 1) / TILE;
    pha_kernel<<<grid, NTHREADS, SMEM_BYTES>>>(P);
}

// round 13
// speedup vs baseline: 2.6554x; 1.0048x over previous
#include <cuda_runtime.h>
#include <cuda_bf16.h>
#include <math.h>
#include <stdint.h>

// ----------------------------------------------------------------------------
// PHomogeneousAutoencoder, mma.sync edition.
// layer2 = bf16x3 split GEMM (AhBh + AhBl + AlBh, fp32 accum) on HMMA
// (mma.sync.m16n8k16). Warp-local dataflow: warp w owns points [16w,16w+16)
// end-to-end; only weight staging needs block barriers.
// R12 change: B fragments via ldmatrix.x4.trans (4 matrices = 2 n-tiles per
// instruction) -- total ldmatrix per warp/stage drops 272 -> 144, attacking
// the measured L1=68% LDSM co-bottleneck.
// ----------------------------------------------------------------------------

#define TILE 256
#define NTHREADS 512
#define HDIM 128
#define ASTB 272    // row stride in bytes (136 bf16); 68 words -> 4-bank skew/row

// SMEM byte offsets
#define OFF_A_HI  0         // 256 x 272 = 69632
#define OFF_A_LO  69632     // 69632
#define OFF_B_HI  139264    // 128 x 272 = 34816  (W2 hi, [k][j])
#define OFF_B_LO  174080    // 34816              (W2 lo, [k][j])
#define OFF_W1    208896    // 3*128 fp32
#define OFF_B1    210432    // 128 fp32
#define OFF_B2    210944    // 128 fp32
#define OFF_W3    211456    // 128*4 fp32 (stride 4)
#define OFF_B3    213504    // 4 fp32
#define OFF_U     213520    // 256*4 fp32
#define OFF_T     217616    // 256*4 fp32
#define SMEM_BYTES 221712

struct Params {
    const float* x;
    const float* center;
    const float* W1[5];
    const float* b1[5];
    const float* W2[5];
    const float* b2[5];
    const float* W3[5];
    const float* b3[5];
    float* out;
    int n;
};

static __device__ __forceinline__ uint32_t smem_u32_of(const void* p) {
    uint32_t a;
    asm("{ .reg .u64 t; cvta.to.shared.u64 t, %1; cvt.u32.u64 %0, t; }" : "=r"(a) : "l"(p));
    return a;
}

static __device__ __forceinline__ void ldsm4(uint32_t& r0, uint32_t& r1, uint32_t& r2,
                                             uint32_t& r3, uint32_t addr) {
    asm volatile("ldmatrix.sync.aligned.m8n8.x4.shared.b16 {%0,%1,%2,%3}, [%4];"
                 : "=r"(r0), "=r"(r1), "=r"(r2), "=r"(r3) : "r"(addr));
}
static __device__ __forceinline__ void ldsm4t(uint32_t& r0, uint32_t& r1, uint32_t& r2,
                                              uint32_t& r3, uint32_t addr) {
    asm volatile("ldmatrix.sync.aligned.m8n8.x4.trans.shared.b16 {%0,%1,%2,%3}, [%4];"
                 : "=r"(r0), "=r"(r1), "=r"(r2), "=r"(r3) : "r"(addr));
}
static __device__ __forceinline__ void mma16816(float* d, uint32_t a0, uint32_t a1,
                                                uint32_t a2, uint32_t a3,
                                                uint32_t b0, uint32_t b1) {
    asm volatile(
        "mma.sync.aligned.m16n8k16.row.col.f32.bf16.bf16.f32 "
        "{%0,%1,%2,%3}, {%4,%5,%6,%7}, {%8,%9}, {%0,%1,%2,%3};"
        : "+f"(d[0]), "+f"(d[1]), "+f"(d[2]), "+f"(d[3])
        : "r"(a0), "r"(a1), "r"(a2), "r"(a3), "r"(b0), "r"(b1));
}

static __device__ __forceinline__ float softplus_f(float x) {
    return fmaxf(x, 0.0f) + log1pf(expf(-fabsf(x)));
}

static __device__ __forceinline__ uint32_t pack_bf(__nv_bfloat16 a, __nv_bfloat16 b) {
    return (uint32_t)__bfloat16_as_ushort(a) | ((uint32_t)__bfloat16_as_ushort(b) << 16);
}

static __device__ __forceinline__ void store2(char* ah, char* al, int col, float x0, float x1) {
    __nv_bfloat16 h0 = __float2bfloat16(x0), h1 = __float2bfloat16(x1);
    __nv_bfloat16 l0 = __float2bfloat16(x0 - __bfloat162float(h0));
    __nv_bfloat16 l1 = __float2bfloat16(x1 - __bfloat162float(h1));
    *(uint32_t*)(ah + col * 2) = pack_bf(h0, h1);
    *(uint32_t*)(al + col * 2) = pack_bf(l0, l1);
}

// Stage weights. Block-wide; sync before (previous readers) and after.
static __device__ void load_weights(char* smem,
                                    const float* __restrict__ W1, const float* __restrict__ b1,
                                    const float* __restrict__ W2, const float* __restrict__ b2,
                                    const float* __restrict__ W3, const float* __restrict__ b3,
                                    int din, int dout) {
    __syncthreads();
    int t = threadIdx.x;
    char* bh = smem + OFF_B_HI;
    char* bl = smem + OFF_B_LO;
#pragma unroll 4
    for (int i = 0; i < 32; i++) {
        int idx = t + NTHREADS * i;          // coalesced over W2[k][j]
        float w = W2[idx];
        int k = idx >> 7, j = idx & 127;
        __nv_bfloat16 h = __float2bfloat16(w);
        __nv_bfloat16 l = __float2bfloat16(w - __bfloat162float(h));
        uint32_t off = (uint32_t)k * ASTB + (uint32_t)j * 2;   // natural [k][j]
        *(__nv_bfloat16*)(bh + off) = h;
        *(__nv_bfloat16*)(bl + off) = l;
    }
    float* W1s = (float*)(smem + OFF_W1);
    for (int i = t; i < din * HDIM; i += NTHREADS) W1s[i] = W1[i];
    if (t < HDIM) {
        ((float*)(smem + OFF_B1))[t] = b1[t];
        ((float*)(smem + OFF_B2))[t] = b2[t];
#pragma unroll 3
        for (int j = 0; j < dout; j++) ((float*)(smem + OFF_W3))[t * 4 + j] = W3[t * dout + j];
    }
    if (t < dout) ((float*)(smem + OFF_B3))[t] = b3[t];
    __syncthreads();
}

// layer1: thread t handles point p=t>>1 (warp-local rows!), 64 cols.
template <int DIN>
static __device__ void layer1(char* smem, const float* __restrict__ in_base) {
    int t = threadIdx.x;
    int p = t >> 1;
    int j0 = (t & 1) * 64;
    const float* W1s = (const float*)(smem + OFF_W1);
    const float* B1s = (const float*)(smem + OFF_B1);
    char* ah = smem + OFF_A_HI + p * ASTB;
    char* al = smem + OFF_A_LO + p * ASTB;
    float in[DIN];
#pragma unroll
    for (int i = 0; i < DIN; i++) in[i] = in_base[p * 4 + i];
#pragma unroll 4
    for (int j = 0; j < 64; j += 4) {
        float4 s = *(const float4*)&B1s[j0 + j];
#pragma unroll
        for (int i = 0; i < DIN; i++) {
            float4 w = *(const float4*)&W1s[i * HDIM + j0 + j];
            s.x = fmaf(in[i], w.x, s.x);
            s.y = fmaf(in[i], w.y, s.y);
            s.z = fmaf(in[i], w.z, s.z);
            s.w = fmaf(in[i], w.w, s.w);
        }
        s.x = fmaxf(s.x, 0.f); s.y = fmaxf(s.y, 0.f);
        s.z = fmaxf(s.z, 0.f); s.w = fmaxf(s.w, 0.f);
        store2(ah, al, j0 + j, s.x, s.y);
        store2(ah, al, j0 + j + 2, s.z, s.w);
    }
}

// bf16x3 MMA over this warp's 16 rows, all 128 cols, K=128.
// A: ldsm4 non-trans on A[row][k]. B: ldsm4t on W2[k][j] -- 4 matrices per
// instruction = fragments for TWO adjacent n-tiles (r0,r1 -> n; r2,r3 -> n+1).
static __device__ void mma_stage(char* smem, float acc[16][4]) {
    int t = threadIdx.x;
    int w = t >> 5, l = t & 31;
    uint32_t aH_base = smem_u32_of(smem + OFF_A_HI) + (uint32_t)(w * 16) * ASTB;
    uint32_t aL_base = smem_u32_of(smem + OFF_A_LO) + (uint32_t)(w * 16) * ASTB;
    uint32_t bH_base = smem_u32_of(smem + OFF_B_HI);
    uint32_t bL_base = smem_u32_of(smem + OFF_B_LO);
    int r = l & 7, sel = l >> 3;
    uint32_t a_off = (uint32_t)((r + (sel & 1) * 8) * ASTB + (sel >> 1) * 16);
    // B lane addr: row = 16ks + (sel&1)*8 + r, col-tile = n + (sel>>1)
    uint32_t b_off = (uint32_t)(((sel & 1) * 8 + r) * ASTB + (sel >> 1) * 16);

#pragma unroll 1
    for (int ks = 0; ks < 8; ks++) {
        uint32_t a_kb = (uint32_t)ks * 32;          // 16 k-cols * 2B in A rows
        uint32_t b_kb = (uint32_t)(ks * 16) * ASTB; // 16 k-rows in B
        uint32_t aH0, aH1, aH2, aH3, aL0, aL1, aL2, aL3;
        ldsm4(aH0, aH1, aH2, aH3, aH_base + a_off + a_kb);
        ldsm4(aL0, aL1, aL2, aL3, aL_base + a_off + a_kb);
#pragma unroll
        for (int n = 0; n < 16; n += 2) {
            uint32_t baddr = b_kb + b_off + (uint32_t)n * 16;
            uint32_t bh0, bh1, bh2, bh3, bl0, bl1, bl2, bl3;
            ldsm4t(bh0, bh1, bh2, bh3, bH_base + baddr);
            ldsm4t(bl0, bl1, bl2, bl3, bL_base + baddr);
            mma16816(acc[n],     aH0, aH1, aH2, aH3, bh0, bh1);
            mma16816(acc[n],     aH0, aH1, aH2, aH3, bl0, bl1);
            mma16816(acc[n],     aL0, aL1, aL2, aL3, bh0, bh1);
            mma16816(acc[n + 1], aH0, aH1, aH2, aH3, bh2, bh3);
            mma16816(acc[n + 1], aH0, aH1, aH2, aH3, bl2, bl3);
            mma16816(acc[n + 1], aL0, aL1, aL2, aL3, bh2, bh3);
        }
    }
}

// Epilogue: bias+ReLU+layer3 straight from fragments; quad shfl reduce.
template <int DOUT>
static __device__ void epilogue(char* smem, float acc[16][4], float* sa, float* sb) {
    const float* B2s = (const float*)(smem + OFF_B2);
    const float* W3s = (const float*)(smem + OFF_W3);
    const float* B3s = (const float*)(smem + OFF_B3);
    int qi = threadIdx.x & 3;
    float sa_[DOUT], sb_[DOUT];
#pragma unroll
    for (int jo = 0; jo < DOUT; jo++) { sa_[jo] = 0.f; sb_[jo] = 0.f; }
#pragma unroll
    for (int n = 0; n < 16; n++) {
        int j = n * 8 + qi * 2;
        float2 b2 = *(const float2*)&B2s[j];
        float vA0 = fmaxf(acc[n][0] + b2.x, 0.f);
        float vA1 = fmaxf(acc[n][1] + b2.y, 0.f);
        float vB0 = fmaxf(acc[n][2] + b2.x, 0.f);
        float vB1 = fmaxf(acc[n][3] + b2.y, 0.f);
        float4 w30 = *(const float4*)&W3s[j * 4];
        float4 w31 = *(const float4*)&W3s[(j + 1) * 4];
        float w30a[4] = {w30.x, w30.y, w30.z, w30.w};
        float w31a[4] = {w31.x, w31.y, w31.z, w31.w};
#pragma unroll
        for (int jo = 0; jo < DOUT; jo++) {
            sa_[jo] = fmaf(vA0, w30a[jo], fmaf(vA1, w31a[jo], sa_[jo]));
            sb_[jo] = fmaf(vB0, w30a[jo], fmaf(vB1, w31a[jo], sb_[jo]));
        }
    }
#pragma unroll
    for (int jo = 0; jo < DOUT; jo++) {
#pragma unroll
        for (int m = 1; m < 4; m <<= 1) {
            sa_[jo] += __shfl_xor_sync(0xFFFFFFFFu, sa_[jo], m);
            sb_[jo] += __shfl_xor_sync(0xFFFFFFFFu, sb_[jo], m);
        }
        sa[jo] = sa_[jo] + B3s[jo];
        sb[jo] = sb_[jo] + B3s[jo];
    }
}

template <int DIN, int DOUT>
static __device__ void run_mlp(char* smem, const Params& P, int m, int in_off,
                               float* sa, float* sb) {
    load_weights(smem, P.W1[m], P.b1[m], P.W2[m], P.b2[m], P.W3[m], P.b3[m], DIN, DOUT);
    layer1<DIN>(smem, (const float*)(smem + in_off));
    __syncwarp();
    float acc[16][4];
#pragma unroll
    for (int n = 0; n < 16; n++)
#pragma unroll
        for (int k = 0; k < 4; k++) acc[n][k] = 0.f;
    mma_stage(smem, acc);
    epilogue<DOUT>(smem, acc, sa, sb);
}

__global__ __launch_bounds__(NTHREADS, 1)
void pha_kernel(Params P) {
    extern __shared__ char smem[];
    int t = threadIdx.x;
    int w = t >> 5, l = t & 31, g = l >> 2, qi = l & 3;
    int pg = blockIdx.x * TILE;
    int la = w * 16 + g, lb = la + 8;       // local point indices (this lane owns 2)
    int pa = pg + la, pb = pg + lb;
    bool live_a = pa < P.n, live_b = pb < P.n;

    float c0 = P.center[0], c1 = P.center[1], c2 = P.center[2];
    float* U = (float*)(smem + OFF_U);
    float* T = (float*)(smem + OFF_T);

    // ---- stage 0: u = unit(x-center), rp = r^2 (lane-owned, qi==0 writes) ----
    float rp_a, rp_b;
    {
        float x0 = 0.f, x1 = 0.f, x2 = 0.f;
        if (live_a) { x0 = P.x[pa*3+0]-c0; x1 = P.x[pa*3+1]-c1; x2 = P.x[pa*3+2]-c2; }
        float r = sqrtf(x0*x0 + x1*x1 + x2*x2);
        float inv = 1.0f / (r + 1e-8f);
        if (qi == 0) { U[la*4+0] = x0*inv; U[la*4+1] = x1*inv; U[la*4+2] = x2*inv; }
        rp_a = r * r;
        x0 = x1 = x2 = 0.f;
        if (live_b) { x0 = P.x[pb*3+0]-c0; x1 = P.x[pb*3+1]-c1; x2 = P.x[pb*3+2]-c2; }
        r = sqrtf(x0*x0 + x1*x1 + x2*x2);
        inv = 1.0f / (r + 1e-8f);
        if (qi == 0) { U[lb*4+0] = x0*inv; U[lb*4+1] = x1*inv; U[lb*4+2] = x2*inv; }
        rp_b = r * r;
    }

    // ---- MLP ea: u -> e (dout=2), unit ----
    float e0a, e1a, e0b, e1b;
    {
        float sa[2], sb[2];
        run_mlp<3, 2>(smem, P, 0, OFF_U, sa, sb);
        float n = sqrtf(sa[0]*sa[0] + sa[1]*sa[1]);
        float inv = 1.0f / (n + 1e-8f);
        e0a = sa[0]*inv; e1a = sa[1]*inv;
        n = sqrtf(sb[0]*sb[0] + sb[1]*sb[1]);
        inv = 1.0f / (n + 1e-8f);
        e0b = sb[0]*inv; e1b = sb[1]*inv;
    }

    // ---- MLP em: u -> a; w, theta, log r_w ----
    float rrec_a, rrec_b;
    {
        float sa[1], sb[1];
        run_mlp<3, 1>(smem, P, 1, OFF_U, sa, sb);
        float a = softplus_f(sa[0]);
        float w0 = rp_a * a * e0a, w1 = rp_a * a * e1a;
        float rw = sqrtf(w0*w0 + w1*w1);
        rrec_a = sqrtf(rw);
        float it = 1.0f / (rw + 1e-8f);
        if (qi == 0) { T[la*4+0] = w0*it; T[la*4+1] = w1*it; T[la*4+2] = logf(rw + 1e-8f); }
        a = softplus_f(sb[0]);
        w0 = rp_b * a * e0b; w1 = rp_b * a * e1b;
        rw = sqrtf(w0*w0 + w1*w1);
        rrec_b = sqrtf(rw);
        it = 1.0f / (rw + 1e-8f);
        if (qi == 0) { T[lb*4+0] = w0*it; T[lb*4+1] = w1*it; T[lb*4+2] = logf(rw + 1e-8f); }
    }

    // ---- MLP db: theta -> c_base (dout=3), unit ----
    float ca0, ca1, ca2, cb0, cb1, cb2;
    {
        float sa[3], sb[3];
        run_mlp<2, 3>(smem, P, 2, OFF_T, sa, sb);
        float n = sqrtf(sa[0]*sa[0] + sa[1]*sa[1] + sa[2]*sa[2]);
        float inv = 1.0f / (n + 1e-8f);
        ca0 = sa[0]*inv; ca1 = sa[1]*inv; ca2 = sa[2]*inv;
        n = sqrtf(sb[0]*sb[0] + sb[1]*sb[1] + sb[2]*sb[2]);
        inv = 1.0f / (n + 1e-8f);
        cb0 = sb[0]*inv; cb1 = sb[1]*inv; cb2 = sb[2]*inv;
    }

    // ---- MLP dc: [theta, log r_w] -> c_corr (dout=3); fold into c_base ----
    {
        float sa[3], sb[3];
        run_mlp<3, 3>(smem, P, 3, OFF_T, sa, sb);
        ca0 += sa[0]; ca1 += sa[1]; ca2 += sa[2];
        cb0 += sb[0]; cb1 += sb[1]; cb2 += sb[2];
    }

    // ---- MLP dm: theta -> b; final output ----
    {
        float sa[1], sb[1];
        run_mlp<2, 1>(smem, P, 4, OFF_T, sa, sb);
        if (qi == 0 && live_a) {
            float b = softplus_f(sa[0]);
            float n = sqrtf(ca0*ca0 + ca1*ca1 + ca2*ca2);
            float scale = rrec_a * b / (n + 1e-8f);
            P.out[pa*3+0] = c0 + scale * ca0;
            P.out[pa*3+1] = c1 + scale * ca1;
            P.out[pa*3+2] = c2 + scale * ca2;
        }
        if (qi == 0 && live_b) {
            float b = softplus_f(sb[0]);
            float n = sqrtf(cb0*cb0 + cb1*cb1 + cb2*cb2);
            float scale = rrec_b * b / (n + 1e-8f);
            P.out[pb*3+0] = c0 + scale * cb0;
            P.out[pb*3+1] = c1 + scale * cb1;
            P.out[pb*3+2] = c2 + scale * cb2;
        }
    }
}

extern "C" void kernel_launch(void* const* d_in, const int* in_sizes, int n_in,
                              void* d_out, int out_size) {
    Params P;
    P.x = (const float*)d_in[0];
    P.center = (const float*)d_in[1];
    for (int m = 0; m < 5; m++) {
        int b = 2 + m * 6;
        P.W1[m] = (const float*)d_in[b + 0];
        P.b1[m] = (const float*)d_in[b + 1];
        P.W2[m] = (const float*)d_in[b + 2];
        P.b2[m] = (const float*)d_in[b + 3];
        P.W3[m] = (const float*)d_in[b + 4];
        P.b3[m] = (const float*)d_in[b + 5];
    }
    P.out = (float*)d_out;
    P.n = in_sizes[0] / 3;

    (void)cudaFuncSetAttribute(pha_kernel, cudaFuncAttributeMaxDynamicSharedMemorySize, SMEM_BYTES);
    int grid = (P.n + TILE - 1) / TILE;
    pha_kernel<<<grid, NTHREADS, SMEM_BYTES>>>(P);
}

// round 14
// speedup vs baseline: 3.9339x; 1.4815x over previous
#include <cuda_runtime.h>
#include <cuda_fp16.h>
#include <math.h>
#include <stdint.h>

// ----------------------------------------------------------------------------
// PHomogeneousAutoencoder, mma.sync fp16x2 pipelined edition.
// layer2 = fp16x2 split GEMM (Ah*Bh + Al*Bh, fp32 accum) on HMMA m16n8k16.
// W2 pre-converted to fp16 once per launch (prep kernel -> __device__ scratch,
// stored in the padded SMEM layout); per-stage staging is cp.async into
// double-buffered B/small-weight SMEM, issued before the MMA phase and waited
// after it -> staging latency hidden behind tensor work.
// Warp-local dataflow: warp w owns points [16w,16w+16) end-to-end.
// ----------------------------------------------------------------------------

#define TILE 256
#define NTHREADS 512
#define HDIM 128
#define ASTB 272          // row stride bytes (128 fp16 data + 16B pad) -> bank skew
#define BTILE_BYTES 34816 // 128 * ASTB

// SMEM byte offsets
#define OFF_A_HI  0            // 256 x 272 = 69632
#define OFF_A_LO  69632        // 69632
#define OFF_B0    139264      // 34816
#define OFF_B1    174080      // 34816
#define OFF_SW0   208896      // 4112
#define OFF_SW1   213008      // 4112
#define OFF_U     217120      // 4096
#define OFF_T     221216      // 4096
#define SMEM_BYTES 225312

// small-weights buffer float offsets
#define SW_W1 0      // up to 3*128
#define SW_B1 384
#define SW_B2 512
#define SW_W3 640    // raw [k*dout + j], up to 384
#define SW_B3 1024   // up to 3

struct Params {
    const float* x;
    const float* center;
    const float* W1[5];
    const float* b1[5];
    const float* W2[5];
    const float* b2[5];
    const float* W3[5];
    const float* b3[5];
    float* out;
    int n;
};

__device__ __align__(16) char g_w2h[5][BTILE_BYTES];

static __device__ __forceinline__ uint32_t smem_u32_of(const void* p) {
    uint32_t a;
    asm("{ .reg .u64 t; cvta.to.shared.u64 t, %1; cvt.u32.u64 %0, t; }" : "=r"(a) : "l"(p));
    return a;
}
static __device__ __forceinline__ void cpa16(uint32_t s, const void* g) {
    asm volatile("cp.async.cg.shared.global [%0], [%1], 16;" :: "r"(s), "l"(g) : "memory");
}
static __device__ __forceinline__ void cpa4(uint32_t s, const void* g) {
    asm volatile("cp.async.ca.shared.global [%0], [%1], 4;" :: "r"(s), "l"(g) : "memory");
}
static __device__ __forceinline__ void cpa_commit() {
    asm volatile("cp.async.commit_group;" ::: "memory");
}
static __device__ __forceinline__ void cpa_wait_all() {
    asm volatile("cp.async.wait_group 0;" ::: "memory");
}

static __device__ __forceinline__ void ldsm4(uint32_t& r0, uint32_t& r1, uint32_t& r2,
                                             uint32_t& r3, uint32_t addr) {
    asm volatile("ldmatrix.sync.aligned.m8n8.x4.shared.b16 {%0,%1,%2,%3}, [%4];"
                 : "=r"(r0), "=r"(r1), "=r"(r2), "=r"(r3) : "r"(addr));
}
static __device__ __forceinline__ void ldsm4t(uint32_t& r0, uint32_t& r1, uint32_t& r2,
                                              uint32_t& r3, uint32_t addr) {
    asm volatile("ldmatrix.sync.aligned.m8n8.x4.trans.shared.b16 {%0,%1,%2,%3}, [%4];"
                 : "=r"(r0), "=r"(r1), "=r"(r2), "=r"(r3) : "r"(addr));
}
static __device__ __forceinline__ void mma16816(float* d, uint32_t a0, uint32_t a1,
                                                uint32_t a2, uint32_t a3,
                                                uint32_t b0, uint32_t b1) {
    asm volatile(
        "mma.sync.aligned.m16n8k16.row.col.f32.f16.f16.f32 "
        "{%0,%1,%2,%3}, {%4,%5,%6,%7}, {%8,%9}, {%0,%1,%2,%3};"
        : "+f"(d[0]), "+f"(d[1]), "+f"(d[2]), "+f"(d[3])
        : "r"(a0), "r"(a1), "r"(a2), "r"(a3), "r"(b0), "r"(b1));
}

static __device__ __forceinline__ float softplus_f(float x) {
    return fmaxf(x, 0.0f) + log1pf(expf(-fabsf(x)));
}
static __device__ __forceinline__ uint32_t pack_h(__half a, __half b) {
    return (uint32_t)__half_as_ushort(a) | ((uint32_t)__half_as_ushort(b) << 16);
}
static __device__ __forceinline__ void store2(char* ah, char* al, int col, float x0, float x1) {
    __half h0 = __float2half(x0), h1 = __float2half(x1);
    __half l0 = __float2half(x0 - __half2float(h0));
    __half l1 = __float2half(x1 - __half2float(h1));
    *(uint32_t*)(ah + col * 2) = pack_h(h0, h1);
    *(uint32_t*)(al + col * 2) = pack_h(l0, l1);
}

// ---- prep kernel: fp32 W2 -> fp16, padded layout, all 5 stages ----
__global__ void prep_kernel(Params P) {
    int idx = blockIdx.x * blockDim.x + threadIdx.x;
    int total = 5 * HDIM * HDIM;
    for (; idx < total; idx += gridDim.x * blockDim.x) {
        int m = idx >> 14, e = idx & 16383;
        int k = e >> 7, j = e & 127;
        *(__half*)(g_w2h[m] + (uint32_t)k * ASTB + (uint32_t)j * 2) = __float2half(P.W2[m][e]);
    }
}

// ---- issue cp.async for stage m's weights (B tile + small weights) ----
static __device__ void stage_weights(char* smem, const Params& P, int m, int din, int dout) {
    int t = threadIdx.x;
    int buf = m & 1;
    uint32_t bdst = smem_u32_of(smem + (buf ? OFF_B1 : OFF_B0));
    const char* gsrc = g_w2h[m];
#pragma unroll
    for (int i = 0; i < 5; i++) {
        int c = t + i * NTHREADS;
        if (c < 2176) cpa16(bdst + (uint32_t)c * 16, gsrc + c * 16);
    }
    uint32_t sw = smem_u32_of(smem + (buf ? OFF_SW1 : OFF_SW0));
    if (t < din * 32) cpa16(sw + SW_W1 * 4 + t * 16, (const char*)P.W1[m] + t * 16);
    else if (t >= 128 && t < 160) cpa16(sw + SW_B1 * 4 + (t - 128) * 16, (const char*)P.b1[m] + (t - 128) * 16);
    else if (t >= 160 && t < 192) cpa16(sw + SW_B2 * 4 + (t - 160) * 16, (const char*)P.b2[m] + (t - 160) * 16);
    else if (t >= 256 && t < 256 + dout * 32) cpa16(sw + SW_W3 * 4 + (t - 256) * 16, (const char*)P.W3[m] + (t - 256) * 16);
    else if (t >= 384 && t < 384 + dout) cpa4(sw + SW_B3 * 4 + (t - 384) * 4, (const char*)P.b3[m] + (t - 384) * 4);
}

// layer1: thread t -> point p=t>>1 (warp-local rows), 64 cols; fp16 hi/lo out.
template <int DIN>
static __device__ void layer1(char* smem, const float* __restrict__ in_base, int m) {
    int t = threadIdx.x;
    int p = t >> 1;
    int j0 = (t & 1) * 64;
    const float* sw = (const float*)(smem + ((m & 1) ? OFF_SW1 : OFF_SW0));
    const float* W1s = sw + SW_W1;
    const float* B1s = sw + SW_B1;
    char* ah = smem + OFF_A_HI + p * ASTB;
    char* al = smem + OFF_A_LO + p * ASTB;
    float in[DIN];
#pragma unroll
    for (int i = 0; i < DIN; i++) in[i] = in_base[p * 4 + i];
#pragma unroll 4
    for (int j = 0; j < 64; j += 4) {
        float4 s = *(const float4*)&B1s[j0 + j];
#pragma unroll
        for (int i = 0; i < DIN; i++) {
            float4 w = *(const float4*)&W1s[i * HDIM + j0 + j];
            s.x = fmaf(in[i], w.x, s.x);
            s.y = fmaf(in[i], w.y, s.y);
            s.z = fmaf(in[i], w.z, s.z);
            s.w = fmaf(in[i], w.w, s.w);
        }
        s.x = fmaxf(s.x, 0.f); s.y = fmaxf(s.y, 0.f);
        s.z = fmaxf(s.z, 0.f); s.w = fmaxf(s.w, 0.f);
        store2(ah, al, j0 + j, s.x, s.y);
        store2(ah, al, j0 + j + 2, s.z, s.w);
    }
}

// fp16x2 MMA: acc += Ah*Bh + Al*Bh over warp's 16 rows, 128 cols, K=128.
static __device__ void mma_stage(char* smem, int bufsel, float acc[16][4]) {
    int t = threadIdx.x;
    int w = t >> 5, l = t & 31;
    uint32_t aH_base = smem_u32_of(smem + OFF_A_HI) + (uint32_t)(w * 16) * ASTB;
    uint32_t aL_base = smem_u32_of(smem + OFF_A_LO) + (uint32_t)(w * 16) * ASTB;
    uint32_t bH_base = smem_u32_of(smem + (bufsel ? OFF_B1 : OFF_B0));
    int r = l & 7, sel = l >> 3;
    uint32_t a_off = (uint32_t)((r + (sel & 1) * 8) * ASTB + (sel >> 1) * 16);
    uint32_t b_off = (uint32_t)(((sel & 1) * 8 + r) * ASTB + (sel >> 1) * 16);

#pragma unroll 1
    for (int ks = 0; ks < 8; ks++) {
        uint32_t a_kb = (uint32_t)ks * 32;          // 16 k-cols * 2B
        uint32_t b_kb = (uint32_t)(ks * 16) * ASTB; // 16 k-rows
        uint32_t aH0, aH1, aH2, aH3, aL0, aL1, aL2, aL3;
        ldsm4(aH0, aH1, aH2, aH3, aH_base + a_off + a_kb);
        ldsm4(aL0, aL1, aL2, aL3, aL_base + a_off + a_kb);
#pragma unroll
        for (int n = 0; n < 16; n += 2) {
            uint32_t baddr = b_kb + b_off + (uint32_t)n * 16;
            uint32_t bh0, bh1, bh2, bh3;
            ldsm4t(bh0, bh1, bh2, bh3, bH_base + baddr);
            mma16816(acc[n],     aH0, aH1, aH2, aH3, bh0, bh1);
            mma16816(acc[n],     aL0, aL1, aL2, aL3, bh0, bh1);
            mma16816(acc[n + 1], aH0, aH1, aH2, aH3, bh2, bh3);
            mma16816(acc[n + 1], aL0, aL1, aL2, aL3, bh2, bh3);
        }
    }
}

// Epilogue: bias+ReLU+layer3 from fragments; quad shfl reduce.
template <int DOUT>
static __device__ void epilogue(char* smem, int m, float acc[16][4], float* sa, float* sb) {
    const float* sw = (const float*)(smem + ((m & 1) ? OFF_SW1 : OFF_SW0));
    const float* B2s = sw + SW_B2;
    const float* W3s = sw + SW_W3;   // raw [k*DOUT + j]
    const float* B3s = sw + SW_B3;
    int qi = threadIdx.x & 3;
    float sa_[DOUT], sb_[DOUT];
#pragma unroll
    for (int jo = 0; jo < DOUT; jo++) { sa_[jo] = 0.f; sb_[jo] = 0.f; }
#pragma unroll
    for (int n = 0; n < 16; n++) {
        int j = n * 8 + qi * 2;
        float2 b2 = *(const float2*)&B2s[j];
        float vA0 = fmaxf(acc[n][0] + b2.x, 0.f);
        float vA1 = fmaxf(acc[n][1] + b2.y, 0.f);
        float vB0 = fmaxf(acc[n][2] + b2.x, 0.f);
        float vB1 = fmaxf(acc[n][3] + b2.y, 0.f);
#pragma unroll
        for (int jo = 0; jo < DOUT; jo++) {
            float w0 = W3s[j * DOUT + jo];
            float w1 = W3s[(j + 1) * DOUT + jo];
            sa_[jo] = fmaf(vA0, w0, fmaf(vA1, w1, sa_[jo]));
            sb_[jo] = fmaf(vB0, w0, fmaf(vB1, w1, sb_[jo]));
        }
    }
#pragma unroll
    for (int jo = 0; jo < DOUT; jo++) {
#pragma unroll
        for (int mm = 1; mm < 4; mm <<= 1) {
            sa_[jo] += __shfl_xor_sync(0xFFFFFFFFu, sa_[jo], mm);
            sb_[jo] += __shfl_xor_sync(0xFFFFFFFFu, sb_[jo], mm);
        }
        sa[jo] = sa_[jo] + B3s[jo];
        sb[jo] = sb_[jo] + B3s[jo];
    }
}

// One stage: layer1 -> issue next stage's staging -> mma -> epilogue.
template <int DIN, int DOUT>
static __device__ void do_stage(char* smem, const Params& P, int m, int in_off,
                                float* sa, float* sb,
                                int next_m, int next_din, int next_dout) {
    layer1<DIN>(smem, (const float*)(smem + in_off), m);
    if (next_m >= 0) {
        stage_weights(smem, P, next_m, next_din, next_dout);
        cpa_commit();
    }
    __syncwarp();
    float acc[16][4];
#pragma unroll
    for (int n = 0; n < 16; n++)
#pragma unroll
        for (int k = 0; k < 4; k++) acc[n][k] = 0.f;
    mma_stage(smem, m & 1, acc);
    epilogue<DOUT>(smem, m, acc, sa, sb);
}

__global__ __launch_bounds__(NTHREADS, 1)
void pha_kernel(Params P) {
    extern __shared__ char smem[];
    int t = threadIdx.x;
    int w = t >> 5, l = t & 31, g = l >> 2, qi = l & 3;
    int pg = blockIdx.x * TILE;
    int la = w * 16 + g, lb = la + 8;
    int pa = pg + la, pb = pg + lb;
    bool live_a = pa < P.n, live_b = pb < P.n;

    float c0 = P.center[0], c1 = P.center[1], c2 = P.center[2];
    float* U = (float*)(smem + OFF_U);
    float* T = (float*)(smem + OFF_T);

    // ---- stage 0 prologue: u = unit(x-center), rp = r^2; stage weights(0) ----
    float rp_a, rp_b;
    {
        float x0 = 0.f, x1 = 0.f, x2 = 0.f;
        if (live_a) { x0 = P.x[pa*3+0]-c0; x1 = P.x[pa*3+1]-c1; x2 = P.x[pa*3+2]-c2; }
        float r = sqrtf(x0*x0 + x1*x1 + x2*x2);
        float inv = 1.0f / (r + 1e-8f);
        if (qi == 0) { U[la*4+0] = x0*inv; U[la*4+1] = x1*inv; U[la*4+2] = x2*inv; }
        rp_a = r * r;
        x0 = x1 = x2 = 0.f;
        if (live_b) { x0 = P.x[pb*3+0]-c0; x1 = P.x[pb*3+1]-c1; x2 = P.x[pb*3+2]-c2; }
        r = sqrtf(x0*x0 + x1*x1 + x2*x2);
        inv = 1.0f / (r + 1e-8f);
        if (qi == 0) { U[lb*4+0] = x0*inv; U[lb*4+1] = x1*inv; U[lb*4+2] = x2*inv; }
        rp_b = r * r;
    }
    stage_weights(smem, P, 0, 3, 2);
    cpa_commit();
    cpa_wait_all();
    __syncthreads();

    // ---- MLP ea (m=0): u -> e, unit ----
    float e0a, e1a, e0b, e1b;
    {
        float sa[2], sb[2];
        do_stage<3, 2>(smem, P, 0, OFF_U, sa, sb, 1, 3, 1);
        float n = sqrtf(sa[0]*sa[0] + sa[1]*sa[1]);
        float inv = 1.0f / (n + 1e-8f);
        e0a = sa[0]*inv; e1a = sa[1]*inv;
        n = sqrtf(sb[0]*sb[0] + sb[1]*sb[1]);
        inv = 1.0f / (n + 1e-8f);
        e0b = sb[0]*inv; e1b = sb[1]*inv;
    }
    cpa_wait_all();
    __syncthreads();

    // ---- MLP em (m=1): u -> a; w, theta, log r_w ----
    float rrec_a, rrec_b;
    {
        float sa[1], sb[1];
        do_stage<3, 1>(smem, P, 1, OFF_U, sa, sb, 2, 2, 3);
        float a = softplus_f(sa[0]);
        float w0 = rp_a * a * e0a, w1 = rp_a * a * e1a;
        float rw = sqrtf(w0*w0 + w1*w1);
        rrec_a = sqrtf(rw);
        float it = 1.0f / (rw + 1e-8f);
        if (qi == 0) { T[la*4+0] = w0*it; T[la*4+1] = w1*it; T[la*4+2] = logf(rw + 1e-8f); }
        a = softplus_f(sb[0]);
        w0 = rp_b * a * e0b; w1 = rp_b * a * e1b;
        rw = sqrtf(w0*w0 + w1*w1);
        rrec_b = sqrtf(rw);
        it = 1.0f / (rw + 1e-8f);
        if (qi == 0) { T[lb*4+0] = w0*it; T[lb*4+1] = w1*it; T[lb*4+2] = logf(rw + 1e-8f); }
    }
    cpa_wait_all();
    __syncthreads();

    // ---- MLP db (m=2): theta -> c_base, unit ----
    float ca0, ca1, ca2, cb0, cb1, cb2;
    {
        float sa[3], sb[3];
        do_stage<2, 3>(smem, P, 2, OFF_T, sa, sb, 3, 3, 3);
        float n = sqrtf(sa[0]*sa[0] + sa[1]*sa[1] + sa[2]*sa[2]);
        float inv = 1.0f / (n + 1e-8f);
        ca0 = sa[0]*inv; ca1 = sa[1]*inv; ca2 = sa[2]*inv;
        n = sqrtf(sb[0]*sb[0] + sb[1]*sb[1] + sb[2]*sb[2]);
        inv = 1.0f / (n + 1e-8f);
        cb0 = sb[0]*inv; cb1 = sb[1]*inv; cb2 = sb[2]*inv;
    }
    cpa_wait_all();
    __syncthreads();

    // ---- MLP dc (m=3): [theta, log r_w] -> c_corr; fold ----
    {
        float sa[3], sb[3];
        do_stage<3, 3>(smem, P, 3, OFF_T, sa, sb, 4, 2, 1);
        ca0 += sa[0]; ca1 += sa[1]; ca2 += sa[2];
        cb0 += sb[0]; cb1 += sb[1]; cb2 += sb[2];
    }
    cpa_wait_all();
    __syncthreads();

    // ---- MLP dm (m=4): theta -> b; final output ----
    {
        float sa[1], sb[1];
        do_stage<2, 1>(smem, P, 4, OFF_T, sa, sb, -1, 0, 0);
        if (qi == 0 && live_a) {
            float b = softplus_f(sa[0]);
            float n = sqrtf(ca0*ca0 + ca1*ca1 + ca2*ca2);
            float scale = rrec_a * b / (n + 1e-8f);
            P.out[pa*3+0] = c0 + scale * ca0;
            P.out[pa*3+1] = c1 + scale * ca1;
            P.out[pa*3+2] = c2 + scale * ca2;
        }
        if (qi == 0 && live_b) {
            float b = softplus_f(sb[0]);
            float n = sqrtf(cb0*cb0 + cb1*cb1 + cb2*cb2);
            float scale = rrec_b * b / (n + 1e-8f);
            P.out[pb*3+0] = c0 + scale * cb0;
            P.out[pb*3+1] = c1 + scale * cb1;
            P.out[pb*3+2] = c2 + scale * cb2;
        }
    }
}

extern "C" void kernel_launch(void* const* d_in, const int* in_sizes, int n_in,
                              void* d_out, int out_size) {
    Params P;
    P.x = (const float*)d_in[0];
    P.center = (const float*)d_in[1];
    for (int m = 0; m < 5; m++) {
        int b = 2 + m * 6;
        P.W1[m] = (const float*)d_in[b + 0];
        P.b1[m] = (const float*)d_in[b + 1];
        P.W2[m] = (const float*)d_in[b + 2];
        P.b2[m] = (const float*)d_in[b + 3];
        P.W3[m] = (const float*)d_in[b + 4];
        P.b3[m] = (const float*)d_in[b + 5];
    }
    P.out = (float*)d_out;
    P.n = in_sizes[0] / 3;

    prep_kernel<<<160, NTHREADS>>>(P);
    (void)cudaFuncSetAttribute(pha_kernel, cudaFuncAttributeMaxDynamicSharedMemorySize, SMEM_BYTES);
    int grid = (P.n + TILE - 1) / TILE;
    pha_kernel<<<grid, NTHREADS, SMEM_BYTES>>>(P);
}

// round 16
// speedup vs baseline: 5.3588x; 1.3622x over previous
#include <cuda_runtime.h>
#include <cuda_fp16.h>
#include <math.h>
#include <stdint.h>

// ----------------------------------------------------------------------------
// PHomogeneousAutoencoder, mma.sync single-pass fp16 edition.
// (Resubmitted; prior round was a broker infra failure, kernel never ran.)
// layer2 = fp16 GEMM (fp32 accum) on HMMA m16n8k16. Error calibration from
// R14: dropped Ah*Bl term measured 1.1e-4; dropping Al*Bh (same magnitude,
// independent) predicts ~1.6-2.5e-4 total, well under the 1e-3 threshold.
// W2 pre-converted to fp16 once per launch (prep kernel); per-stage staging is
// cp.async into double-buffered SMEM, issued before the MMA phase and waited
// after it. Warp-local dataflow: warp w owns points [16w,16w+16) end-to-end.
// ----------------------------------------------------------------------------

#define TILE 256
#define NTHREADS 512
#define HDIM 128
#define ASTB 272          // row stride bytes (128 fp16 + 16B pad) -> bank skew
#define BTILE_BYTES 34816 // 128 * ASTB

// SMEM byte offsets
#define OFF_A     0           // 256 x 272 = 69632
#define OFF_B0    69632       // 34816
#define OFF_B1    104448      // 34816
#define OFF_SW0   139264      // 4112
#define OFF_SW1   143376      // 4112
#define OFF_U     147488      // 4096
#define OFF_T     151584      // 4096
#define SMEM_BYTES 155680

// small-weights buffer float offsets
#define SW_W1 0      // up to 3*128
#define SW_B1 384
#define SW_B2 512
#define SW_W3 640    // raw [k*dout + j], up to 384
#define SW_B3 1024   // up to 3

struct Params {
    const float* x;
    const float* center;
    const float* W1[5];
    const float* b1[5];
    const float* W2[5];
    const float* b2[5];
    const float* W3[5];
    const float* b3[5];
    float* out;
    int n;
};

__device__ __align__(16) char g_w2h[5][BTILE_BYTES];

static __device__ __forceinline__ uint32_t smem_u32_of(const void* p) {
    uint32_t a;
    asm("{ .reg .u64 t; cvta.to.shared.u64 t, %1; cvt.u32.u64 %0, t; }" : "=r"(a) : "l"(p));
    return a;
}
static __device__ __forceinline__ void cpa16(uint32_t s, const void* g) {
    asm volatile("cp.async.cg.shared.global [%0], [%1], 16;" :: "r"(s), "l"(g) : "memory");
}
static __device__ __forceinline__ void cpa4(uint32_t s, const void* g) {
    asm volatile("cp.async.ca.shared.global [%0], [%1], 4;" :: "r"(s), "l"(g) : "memory");
}
static __device__ __forceinline__ void cpa_commit() {
    asm volatile("cp.async.commit_group;" ::: "memory");
}
static __device__ __forceinline__ void cpa_wait_all() {
    asm volatile("cp.async.wait_group 0;" ::: "memory");
}

static __device__ __forceinline__ void ldsm4(uint32_t& r0, uint32_t& r1, uint32_t& r2,
                                             uint32_t& r3, uint32_t addr) {
    asm volatile("ldmatrix.sync.aligned.m8n8.x4.shared.b16 {%0,%1,%2,%3}, [%4];"
                 : "=r"(r0), "=r"(r1), "=r"(r2), "=r"(r3) : "r"(addr));
}
static __device__ __forceinline__ void ldsm4t(uint32_t& r0, uint32_t& r1, uint32_t& r2,
                                              uint32_t& r3, uint32_t addr) {
    asm volatile("ldmatrix.sync.aligned.m8n8.x4.trans.shared.b16 {%0,%1,%2,%3}, [%4];"
                 : "=r"(r0), "=r"(r1), "=r"(r2), "=r"(r3) : "r"(addr));
}
static __device__ __forceinline__ void mma16816(float* d, uint32_t a0, uint32_t a1,
                                                uint32_t a2, uint32_t a3,
                                                uint32_t b0, uint32_t b1) {
    asm volatile(
        "mma.sync.aligned.m16n8k16.row.col.f32.f16.f16.f32 "
        "{%0,%1,%2,%3}, {%4,%5,%6,%7}, {%8,%9}, {%0,%1,%2,%3};"
        : "+f"(d[0]), "+f"(d[1]), "+f"(d[2]), "+f"(d[3])
        : "r"(a0), "r"(a1), "r"(a2), "r"(a3), "r"(b0), "r"(b1));
}

static __device__ __forceinline__ float softplus_f(float x) {
    return fmaxf(x, 0.0f) + log1pf(expf(-fabsf(x)));
}
static __device__ __forceinline__ uint32_t pack_h(__half a, __half b) {
    return (uint32_t)__half_as_ushort(a) | ((uint32_t)__half_as_ushort(b) << 16);
}

// ---- prep kernel: fp32 W2 -> fp16, padded layout, all 5 stages ----
__global__ void prep_kernel(Params P) {
    int idx = blockIdx.x * blockDim.x + threadIdx.x;
    int total = 5 * HDIM * HDIM;
    for (; idx < total; idx += gridDim.x * blockDim.x) {
        int m = idx >> 14, e = idx & 16383;
        int k = e >> 7, j = e & 127;
        *(__half*)(g_w2h[m] + (uint32_t)k * ASTB + (uint32_t)j * 2) = __float2half(P.W2[m][e]);
    }
}

// ---- issue cp.async for stage m's weights (B tile + small weights) ----
static __device__ void stage_weights(char* smem, const Params& P, int m, int din, int dout) {
    int t = threadIdx.x;
    int buf = m & 1;
    uint32_t bdst = smem_u32_of(smem + (buf ? OFF_B1 : OFF_B0));
    const char* gsrc = g_w2h[m];
#pragma unroll
    for (int i = 0; i < 5; i++) {
        int c = t + i * NTHREADS;
        if (c < 2176) cpa16(bdst + (uint32_t)c * 16, gsrc + c * 16);
    }
    uint32_t sw = smem_u32_of(smem + (buf ? OFF_SW1 : OFF_SW0));
    if (t < din * 32) cpa16(sw + SW_W1 * 4 + t * 16, (const char*)P.W1[m] + t * 16);
    else if (t >= 128 && t < 160) cpa16(sw + SW_B1 * 4 + (t - 128) * 16, (const char*)P.b1[m] + (t - 128) * 16);
    else if (t >= 160 && t < 192) cpa16(sw + SW_B2 * 4 + (t - 160) * 16, (const char*)P.b2[m] + (t - 160) * 16);
    else if (t >= 256 && t < 256 + dout * 32) cpa16(sw + SW_W3 * 4 + (t - 256) * 16, (const char*)P.W3[m] + (t - 256) * 16);
    else if (t >= 384 && t < 384 + dout) cpa4(sw + SW_B3 * 4 + (t - 384) * 4, (const char*)P.b3[m] + (t - 384) * 4);
}

// layer1: thread t -> point p=t>>1 (warp-local rows), 64 cols; fp16 out.
template <int DIN>
static __device__ void layer1(char* smem, const float* __restrict__ in_base, int m) {
    int t = threadIdx.x;
    int p = t >> 1;
    int j0 = (t & 1) * 64;
    const float* sw = (const float*)(smem + ((m & 1) ? OFF_SW1 : OFF_SW0));
    const float* W1s = sw + SW_W1;
    const float* B1s = sw + SW_B1;
    char* arow = smem + OFF_A + p * ASTB;
    float in[DIN];
#pragma unroll
    for (int i = 0; i < DIN; i++) in[i] = in_base[p * 4 + i];
#pragma unroll 4
    for (int j = 0; j < 64; j += 4) {
        float4 s = *(const float4*)&B1s[j0 + j];
#pragma unroll
        for (int i = 0; i < DIN; i++) {
            float4 w = *(const float4*)&W1s[i * HDIM + j0 + j];
            s.x = fmaf(in[i], w.x, s.x);
            s.y = fmaf(in[i], w.y, s.y);
            s.z = fmaf(in[i], w.z, s.z);
            s.w = fmaf(in[i], w.w, s.w);
        }
        s.x = fmaxf(s.x, 0.f); s.y = fmaxf(s.y, 0.f);
        s.z = fmaxf(s.z, 0.f); s.w = fmaxf(s.w, 0.f);
        uint32_t p0 = pack_h(__float2half(s.x), __float2half(s.y));
        uint32_t p1 = pack_h(__float2half(s.z), __float2half(s.w));
        *(uint2*)(arow + (j0 + j) * 2) = make_uint2(p0, p1);
    }
}

// fp16 MMA: acc += A*B over warp's 16 rows, 128 cols, K=128.
static __device__ void mma_stage(char* smem, int bufsel, float acc[16][4]) {
    int t = threadIdx.x;
    int w = t >> 5, l = t & 31;
    uint32_t a_base = smem_u32_of(smem + OFF_A) + (uint32_t)(w * 16) * ASTB;
    uint32_t b_base = smem_u32_of(smem + (bufsel ? OFF_B1 : OFF_B0));
    int r = l & 7, sel = l >> 3;
    uint32_t a_off = (uint32_t)((r + (sel & 1) * 8) * ASTB + (sel >> 1) * 16);
    uint32_t b_off = (uint32_t)(((sel & 1) * 8 + r) * ASTB + (sel >> 1) * 16);

#pragma unroll 1
    for (int ks = 0; ks < 8; ks++) {
        uint32_t a_kb = (uint32_t)ks * 32;          // 16 k-cols * 2B
        uint32_t b_kb = (uint32_t)(ks * 16) * ASTB; // 16 k-rows
        uint32_t a0, a1, a2, a3;
        ldsm4(a0, a1, a2, a3, a_base + a_off + a_kb);
#pragma unroll
        for (int n = 0; n < 16; n += 2) {
            uint32_t baddr = b_kb + b_off + (uint32_t)n * 16;
            uint32_t b0, b1, b2, b3;
            ldsm4t(b0, b1, b2, b3, b_base + baddr);
            mma16816(acc[n],     a0, a1, a2, a3, b0, b1);
            mma16816(acc[n + 1], a0, a1, a2, a3, b2, b3);
        }
    }
}

// Epilogue: bias+ReLU+layer3 from fragments; quad shfl reduce.
template <int DOUT>
static __device__ void epilogue(char* smem, int m, float acc[16][4], float* sa, float* sb) {
    const float* sw = (const float*)(smem + ((m & 1) ? OFF_SW1 : OFF_SW0));
    const float* B2s = sw + SW_B2;
    const float* W3s = sw + SW_W3;   // raw [k*DOUT + j]
    const float* B3s = sw + SW_B3;
    int qi = threadIdx.x & 3;
    float sa_[DOUT], sb_[DOUT];
#pragma unroll
    for (int jo = 0; jo < DOUT; jo++) { sa_[jo] = 0.f; sb_[jo] = 0.f; }
#pragma unroll
    for (int n = 0; n < 16; n++) {
        int j = n * 8 + qi * 2;
        float2 b2 = *(const float2*)&B2s[j];
        float vA0 = fmaxf(acc[n][0] + b2.x, 0.f);
        float vA1 = fmaxf(acc[n][1] + b2.y, 0.f);
        float vB0 = fmaxf(acc[n][2] + b2.x, 0.f);
        float vB1 = fmaxf(acc[n][3] + b2.y, 0.f);
#pragma unroll
        for (int jo = 0; jo < DOUT; jo++) {
            float w0 = W3s[j * DOUT + jo];
            float w1 = W3s[(j + 1) * DOUT + jo];
            sa_[jo] = fmaf(vA0, w0, fmaf(vA1, w1, sa_[jo]));
            sb_[jo] = fmaf(vB0, w0, fmaf(vB1, w1, sb_[jo]));
        }
    }
#pragma unroll
    for (int jo = 0; jo < DOUT; jo++) {
#pragma unroll
        for (int mm = 1; mm < 4; mm <<= 1) {
            sa_[jo] += __shfl_xor_sync(0xFFFFFFFFu, sa_[jo], mm);
            sb_[jo] += __shfl_xor_sync(0xFFFFFFFFu, sb_[jo], mm);
        }
        sa[jo] = sa_[jo] + B3s[jo];
        sb[jo] = sb_[jo] + B3s[jo];
    }
}

// One stage: layer1 -> issue next stage's staging -> mma -> epilogue.
template <int DIN, int DOUT>
static __device__ void do_stage(char* smem, const Params& P, int m, int in_off,
                                float* sa, float* sb,
                                int next_m, int next_din, int next_dout) {
    layer1<DIN>(smem, (const float*)(smem + in_off), m);
    if (next_m >= 0) {
        stage_weights(smem, P, next_m, next_din, next_dout);
        cpa_commit();
    }
    __syncwarp();
    float acc[16][4];
#pragma unroll
    for (int n = 0; n < 16; n++)
#pragma unroll
        for (int k = 0; k < 4; k++) acc[n][k] = 0.f;
    mma_stage(smem, m & 1, acc);
    epilogue<DOUT>(smem, m, acc, sa, sb);
}

__global__ __launch_bounds__(NTHREADS, 1)
void pha_kernel(Params P) {
    extern __shared__ char smem[];
    int t = threadIdx.x;
    int w = t >> 5, l = t & 31, g = l >> 2, qi = l & 3;
    int pg = blockIdx.x * TILE;
    int la = w * 16 + g, lb = la + 8;
    int pa = pg + la, pb = pg + lb;
    bool live_a = pa < P.n, live_b = pb < P.n;

    float c0 = P.center[0], c1 = P.center[1], c2 = P.center[2];
    float* U = (float*)(smem + OFF_U);
    float* T = (float*)(smem + OFF_T);

    // ---- stage 0 prologue: u = unit(x-center), rp = r^2; stage weights(0) ----
    float rp_a, rp_b;
    {
        float x0 = 0.f, x1 = 0.f, x2 = 0.f;
        if (live_a) { x0 = P.x[pa*3+0]-c0; x1 = P.x[pa*3+1]-c1; x2 = P.x[pa*3+2]-c2; }
        float r = sqrtf(x0*x0 + x1*x1 + x2*x2);
        float inv = 1.0f / (r + 1e-8f);
        if (qi == 0) { U[la*4+0] = x0*inv; U[la*4+1] = x1*inv; U[la*4+2] = x2*inv; }
        rp_a = r * r;
        x0 = x1 = x2 = 0.f;
        if (live_b) { x0 = P.x[pb*3+0]-c0; x1 = P.x[pb*3+1]-c1; x2 = P.x[pb*3+2]-c2; }
        r = sqrtf(x0*x0 + x1*x1 + x2*x2);
        inv = 1.0f / (r + 1e-8f);
        if (qi == 0) { U[lb*4+0] = x0*inv; U[lb*4+1] = x1*inv; U[lb*4+2] = x2*inv; }
        rp_b = r * r;
    }
    stage_weights(smem, P, 0, 3, 2);
    cpa_commit();
    cpa_wait_all();
    __syncthreads();

    // ---- MLP ea (m=0): u -> e, unit ----
    float e0a, e1a, e0b, e1b;
    {
        float sa[2], sb[2];
        do_stage<3, 2>(smem, P, 0, OFF_U, sa, sb, 1, 3, 1);
        float n = sqrtf(sa[0]*sa[0] + sa[1]*sa[1]);
        float inv = 1.0f / (n + 1e-8f);
        e0a = sa[0]*inv; e1a = sa[1]*inv;
        n = sqrtf(sb[0]*sb[0] + sb[1]*sb[1]);
        inv = 1.0f / (n + 1e-8f);
        e0b = sb[0]*inv; e1b = sb[1]*inv;
    }
    cpa_wait_all();
    __syncthreads();

    // ---- MLP em (m=1): u -> a; w, theta, log r_w ----
    float rrec_a, rrec_b;
    {
        float sa[1], sb[1];
        do_stage<3, 1>(smem, P, 1, OFF_U, sa, sb, 2, 2, 3);
        float a = softplus_f(sa[0]);
        float w0 = rp_a * a * e0a, w1 = rp_a * a * e1a;
        float rw = sqrtf(w0*w0 + w1*w1);
        rrec_a = sqrtf(rw);
        float it = 1.0f / (rw + 1e-8f);
        if (qi == 0) { T[la*4+0] = w0*it; T[la*4+1] = w1*it; T[la*4+2] = logf(rw + 1e-8f); }
        a = softplus_f(sb[0]);
        w0 = rp_b * a * e0b; w1 = rp_b * a * e1b;
        rw = sqrtf(w0*w0 + w1*w1);
        rrec_b = sqrtf(rw);
        it = 1.0f / (rw + 1e-8f);
        if (qi == 0) { T[lb*4+0] = w0*it; T[lb*4+1] = w1*it; T[lb*4+2] = logf(rw + 1e-8f); }
    }
    cpa_wait_all();
    __syncthreads();

    // ---- MLP db (m=2): theta -> c_base, unit ----
    float ca0, ca1, ca2, cb0, cb1, cb2;
    {
        float sa[3], sb[3];
        do_stage<2, 3>(smem, P, 2, OFF_T, sa, sb, 3, 3, 3);
        float n = sqrtf(sa[0]*sa[0] + sa[1]*sa[1] + sa[2]*sa[2]);
        float inv = 1.0f / (n + 1e-8f);
        ca0 = sa[0]*inv; ca1 = sa[1]*inv; ca2 = sa[2]*inv;
        n = sqrtf(sb[0]*sb[0] + sb[1]*sb[1] + sb[2]*sb[2]);
        inv = 1.0f / (n + 1e-8f);
        cb0 = sb[0]*inv; cb1 = sb[1]*inv; cb2 = sb[2]*inv;
    }
    cpa_wait_all();
    __syncthreads();

    // ---- MLP dc (m=3): [theta, log r_w] -> c_corr; fold ----
    {
        float sa[3], sb[3];
        do_stage<3, 3>(smem, P, 3, OFF_T, sa, sb, 4, 2, 1);
        ca0 += sa[0]; ca1 += sa[1]; ca2 += sa[2];
        cb0 += sb[0]; cb1 += sb[1]; cb2 += sb[2];
    }
    cpa_wait_all();
    __syncthreads();

    // ---- MLP dm (m=4): theta -> b; final output ----
    {
        float sa[1], sb[1];
        do_stage<2, 1>(smem, P, 4, OFF_T, sa, sb, -1, 0, 0);
        if (qi == 0 && live_a) {
            float b = softplus_f(sa[0]);
            float n = sqrtf(ca0*ca0 + ca1*ca1 + ca2*ca2);
            float scale = rrec_a * b / (n + 1e-8f);
            P.out[pa*3+0] = c0 + scale * ca0;
            P.out[pa*3+1] = c1 + scale * ca1;
            P.out[pa*3+2] = c2 + scale * ca2;
        }
        if (qi == 0 && live_b) {
            float b = softplus_f(sb[0]);
            float n = sqrtf(cb0*cb0 + cb1*cb1 + cb2*cb2);
            float scale = rrec_b * b / (n + 1e-8f);
            P.out[pb*3+0] = c0 + scale * cb0;
            P.out[pb*3+1] = c1 + scale * cb1;
            P.out[pb*3+2] = c2 + scale * cb2;
        }
    }
}

extern "C" void kernel_launch(void* const* d_in, const int* in_sizes, int n_in,
                              void* d_out, int out_size) {
    Params P;
    P.x = (const float*)d_in[0];
    P.center = (const float*)d_in[1];
    for (int m = 0; m < 5; m++) {
        int b = 2 + m * 6;
        P.W1[m] = (const float*)d_in[b + 0];
        P.b1[m] = (const float*)d_in[b + 1];
        P.W2[m] = (const float*)d_in[b + 2];
        P.b2[m] = (const float*)d_in[b + 3];
        P.W3[m] = (const float*)d_in[b + 4];
        P.b3[m] = (const float*)d_in[b + 5];
    }
    P.out = (float*)d_out;
    P.n = in_sizes[0] / 3;

    prep_kernel<<<160, NTHREADS>>>(P);
    (void)cudaFuncSetAttribute(pha_kernel, cudaFuncAttributeMaxDynamicSharedMemorySize, SMEM_BYTES);
    int grid = (P.n + TILE - 1) / TILE;
    pha_kernel<<<grid, NTHREADS, SMEM_BYTES>>>(P);
}